// round 1
// baseline (speedup 1.0000x reference)
#include <cuda_runtime.h>
#include <math.h>

#define NC   128
#define HH   512
#define WW   512
#define NHW  (HH*WW)
#define MAXN 10000

// ---------------- persistent device state (no dynamic allocation) ----------------
__device__ float  g_fqT[NC * NHW];        // feature map transposed to (pixel, channel)
__device__ float  g_p2init[2 * MAXN];     // projection at iteration 0
__device__ double g_acc[29];              // [0..20] Hess upper-tri, [21..26] Grad, [27] cost*vf, [28] vf
__device__ double g_tacc[2];              // trial cost*vf, vf
__device__ double g_R[9], g_t[3], g_Rn[9], g_tn[3];
__device__ double g_lam, g_costbest, g_jac[6];

// ---------------- helpers ----------------
template <int NV>
__device__ __forceinline__ void warpReduce(float* v) {
#pragma unroll
    for (int off = 16; off > 0; off >>= 1) {
#pragma unroll
        for (int i = 0; i < NV; i++) v[i] += __shfl_down_sync(0xffffffffu, v[i], off);
    }
}

__device__ __forceinline__ bool inImage(float px, float py) {
    return (px >= 1.0f) && (px < 511.0f) && (py >= 1.0f) && (py < 511.0f);
}

// 2x2 bilinear footprint (reference-exact clipping semantics)
__device__ __forceinline__ void bilin4(float px, float py, int* o, float* w) {
    float x0f = fminf(fmaxf(floorf(px), 0.0f), 511.0f);
    float y0f = fminf(fmaxf(floorf(py), 0.0f), 511.0f);
    float x1f = fminf(x0f + 1.0f, 511.0f);
    float y1f = fminf(y0f + 1.0f, 511.0f);
    float wx = px - x0f, wy = py - y0f;
    int x0 = (int)x0f, x1 = (int)x1f, y0 = (int)y0f, y1 = (int)y1f;
    o[0] = (y0 * WW + x0) * NC;
    o[1] = (y0 * WW + x1) * NC;
    o[2] = (y1 * WW + x0) * NC;
    o[3] = (y1 * WW + x1) * NC;
    w[0] = (1.0f - wx) * (1.0f - wy);
    w[1] = wx * (1.0f - wy);
    w[2] = (1.0f - wx) * wy;
    w[3] = wx * wy;
}

// ---------------- init ----------------
__global__ void k_init(const float* __restrict__ R0, const float* __restrict__ t0) {
    int i = threadIdx.x;
    if (i < 9)  g_R[i] = (double)R0[i];
    if (i < 3)  g_t[i] = (double)t0[i];
    if (i == 0) g_lam = 0.01;
    if (i < 29) g_acc[i] = 0.0;
    if (i < 2)  g_tacc[i] = 0.0;
}

// ---------------- transpose (C,H,W) -> (H*W, C) ----------------
__global__ void __launch_bounds__(256) k_transpose(const float* __restrict__ fq) {
    __shared__ float sh[64][NC + 1];
    int pix0 = blockIdx.x * 64;
    int tid = threadIdx.x;
    int px = tid & 63;
    int crow = tid >> 6;  // 0..3
#pragma unroll
    for (int cb = 0; cb < NC; cb += 4) {
        int c = cb + crow;
        sh[px][c] = fq[c * NHW + pix0 + px];
    }
    __syncthreads();
    int c2 = tid & 127;
    int prow = tid >> 7;  // 0..1
#pragma unroll
    for (int pb = 0; pb < 64; pb += 2) {
        int p = pb + prow;
        g_fqT[(pix0 + p) * NC + c2] = sh[p][c2];
    }
}

// ---------------- main LM accumulation kernel ----------------
__global__ void __launch_bounds__(256) k_main(const float* __restrict__ p3D,
                                              const float* __restrict__ fref,
                                              const float* __restrict__ Km,
                                              int N, int isIter0) {
    __shared__ double sh[29];
    int tid = threadIdx.x;
    if (tid < 29) sh[tid] = 0.0;
    __syncthreads();
    int lane = tid & 31, warp = tid >> 5;
    int wg = blockIdx.x * 8 + warp;
    int nw = gridDim.x * 8;
    float fx = Km[0], fy = Km[4], cx = Km[2], cy = Km[5];
    double R[9], T[3];
#pragma unroll
    for (int i = 0; i < 9; i++) R[i] = g_R[i];
#pragma unroll
    for (int i = 0; i < 3; i++) T[i] = g_t[i];

    for (int pt = wg; pt < N; pt += nw) {
        float Px = p3D[3 * pt + 0], Py = p3D[3 * pt + 1], Pz = p3D[3 * pt + 2];
        double xd = R[0] * Px + R[1] * Py + R[2] * Pz + T[0];
        double yd = R[3] * Px + R[4] * Py + R[5] * Pz + T[1];
        double zd = R[6] * Px + R[7] * Py + R[8] * Pz + T[2];
        double izd = 1.0 / zd;
        float px = (float)(xd * izd * (double)fx + (double)cx);
        float py = (float)(yd * izd * (double)fy + (double)cy);
        if (isIter0 && lane == 0) {
            g_p2init[2 * pt]     = px;
            g_p2init[2 * pt + 1] = py;
        }
        if (!inImage(px, py)) continue;   // vf = 0: contributes nothing

        // 4x4 patch footprint (bilinear corners + sobel halo), edge-clamped
        float x0f = fminf(fmaxf(floorf(px), 0.0f), 511.0f);
        float y0f = fminf(fmaxf(floorf(py), 0.0f), 511.0f);
        float x1f = fminf(x0f + 1.0f, 511.0f);
        float y1f = fminf(y0f + 1.0f, 511.0f);
        float wx = px - x0f, wy = py - y0f;
        int x0 = (int)x0f, x1 = (int)x1f, y0 = (int)y0f, y1 = (int)y1f;
        int cs[4] = {x0 > 0 ? x0 - 1 : 0, x0, x1, x1 < 511 ? x1 + 1 : 511};
        int rs[4] = {y0 > 0 ? y0 - 1 : 0, y0, y1, y1 < 511 ? y1 + 1 : 511};
        int offs[16];
#pragma unroll
        for (int i = 0; i < 4; i++)
#pragma unroll
            for (int j = 0; j < 4; j++) offs[i * 4 + j] = (rs[i] * WW + cs[j]) * NC;
        float w00 = (1.0f - wx) * (1.0f - wy), w01 = wx * (1.0f - wy);
        float w10 = (1.0f - wx) * wy,          w11 = wx * wy;

        float acc[10];
#pragma unroll
        for (int i = 0; i < 10; i++) acc[i] = 0.0f;

#pragma unroll
        for (int k = 0; k < 4; k++) {
            int c = lane + 32 * k;
            const float* B = g_fqT + c;
            float p00 = __ldg(B + offs[0]),  p01 = __ldg(B + offs[1]);
            float p02 = __ldg(B + offs[2]),  p03 = __ldg(B + offs[3]);
            float p10 = __ldg(B + offs[4]),  p11 = __ldg(B + offs[5]);
            float p12 = __ldg(B + offs[6]),  p13 = __ldg(B + offs[7]);
            float p20 = __ldg(B + offs[8]),  p21 = __ldg(B + offs[9]);
            float p22 = __ldg(B + offs[10]), p23 = __ldg(B + offs[11]);
            float p30 = __ldg(B + offs[12]), p31 = __ldg(B + offs[13]);
            float p32 = __ldg(B + offs[14]), p33 = __ldg(B + offs[15]);

            float fb = w00 * p11 + w01 * p12 + w10 * p21 + w11 * p22;
            float gx00 = ((p02 - p00) + 2.0f * (p12 - p10) + (p22 - p20)) * 0.125f;
            float gx01 = ((p03 - p01) + 2.0f * (p13 - p11) + (p23 - p21)) * 0.125f;
            float gx10 = ((p12 - p10) + 2.0f * (p22 - p20) + (p32 - p30)) * 0.125f;
            float gx11 = ((p13 - p11) + 2.0f * (p23 - p21) + (p33 - p31)) * 0.125f;
            float gy00 = ((p20 - p00) + 2.0f * (p21 - p01) + (p22 - p02)) * 0.125f;
            float gy01 = ((p21 - p01) + 2.0f * (p22 - p02) + (p23 - p03)) * 0.125f;
            float gy10 = ((p30 - p10) + 2.0f * (p31 - p11) + (p32 - p12)) * 0.125f;
            float gy11 = ((p31 - p11) + 2.0f * (p32 - p12) + (p33 - p13)) * 0.125f;
            float gxb = w00 * gx00 + w01 * gx01 + w10 * gx10 + w11 * gx11;
            float gyb = w00 * gy00 + w01 * gy01 + w10 * gy10 + w11 * gy11;
            float r = __ldg(fref + pt * NC + c);

            acc[0] += fb * fb;   acc[1] += fb * gxb;  acc[2] += fb * gyb;
            acc[3] += gxb * gxb; acc[4] += gxb * gyb; acc[5] += gyb * gyb;
            acc[6] += gxb * r;   acc[7] += gyb * r;   acc[8] += fb * r;
            acc[9] += r * r;
        }
        warpReduce<10>(acc);

        if (lane == 0) {
            double n2 = acc[0], a = acc[1], b = acc[2];
            double Sxx = acc[3], Sxy = acc[4], Syy = acc[5];
            double ux = acc[6], uy = acc[7], sdot = acc[8], rn2 = acc[9];
            double norm  = fmax(sqrt(n2), 1e-12);
            double rnorm = fmax(sqrt(rn2), 1e-12);
            double inorm = 1.0 / norm, irn = 1.0 / rnorm;
            double projx = a * inorm, projy = b * inorm;
            double nf2 = n2 * inorm * inorm;
            double s = sdot * inorm * irn;
            double errsq = nf2 - 2.0 * s + rn2 * irn * irn;
            double fac = 2.0 - nf2;
            double in2 = inorm * inorm;
            double Mxx = (Sxx - projx * projx * fac) * in2;
            double Mxy = (Sxy - projx * projy * fac) * in2;
            double Myy = (Syy - projy * projy * fac) * in2;
            double coef = 1.0 - nf2 + s;
            double g2x = (projx * coef - ux * irn) * inorm;
            double g2y = (projy * coef - uy * irn) * inorm;

            double Jpn00 = (double)fx * izd;
            double Jpn02 = -(double)fx * xd * izd * izd;
            double Jpn11 = (double)fy * izd;
            double Jpn12 = -(double)fy * yd * izd * izd;
            double J0[6] = {Jpn00, 0.0, Jpn02, Jpn02 * yd, Jpn00 * zd - Jpn02 * xd, -Jpn00 * yd};
            double J1[6] = {0.0, Jpn11, Jpn12, -Jpn11 * zd + Jpn12 * yd, -Jpn12 * xd, Jpn11 * xd};

            int idx = 0;
#pragma unroll
            for (int i = 0; i < 6; i++) {
                double mi0 = Mxx * J0[i] + Mxy * J1[i];
                double mi1 = Mxy * J0[i] + Myy * J1[i];
#pragma unroll
                for (int j = 0; j < 6; j++) {
                    if (j >= i) atomicAdd(&sh[idx++], mi0 * J0[j] + mi1 * J1[j]);
                }
            }
#pragma unroll
            for (int j = 0; j < 6; j++)
                atomicAdd(&sh[21 + j], g2x * J0[j] + g2y * J1[j]);
            atomicAdd(&sh[27], errsq);
            atomicAdd(&sh[28], 1.0);
        }
    }
    __syncthreads();
    if (tid < 29) atomicAdd(&g_acc[tid], sh[tid]);
}

// ---------------- solve: jacobi, damping, 6x6 LU, SO3 update ----------------
__global__ void k_solve(int iter) {
    double Hp[21], G[6];
    for (int i = 0; i < 21; i++) Hp[i] = g_acc[i];
    for (int i = 0; i < 6; i++)  G[i] = g_acc[21 + i];
    double cs = g_acc[27], vs = g_acc[28];
    if (iter == 0) {
        g_costbest = cs / vs;
        int idx = 0;
        for (int i = 0; i < 6; i++)
            for (int j = i; j < 6; j++) {
                if (j == i) g_jac[i] = 1.0 / (1.0 + sqrt(Hp[idx]));
                idx++;
            }
    }
    double jac[6];
    for (int i = 0; i < 6; i++) jac[i] = g_jac[i];

    double A[6][7];
    {
        int idx = 0;
        for (int i = 0; i < 6; i++)
            for (int j = i; j < 6; j++) {
                double v = Hp[idx++] * jac[i] * jac[j];
                A[i][j] = v;
                A[j][i] = v;
            }
    }
    double lam = g_lam;
    for (int i = 0; i < 6; i++) {
        double d = A[i][i];
        A[i][i] = d + (d + 1e-9) * lam;
        A[i][6] = -G[i] * jac[i];
    }
    // Gaussian elimination with partial pivoting
    for (int col = 0; col < 6; col++) {
        int piv = col;
        double best = fabs(A[col][col]);
        for (int r2 = col + 1; r2 < 6; r2++) {
            double v = fabs(A[r2][col]);
            if (v > best) { best = v; piv = r2; }
        }
        if (piv != col)
            for (int j = col; j < 7; j++) { double t = A[col][j]; A[col][j] = A[piv][j]; A[piv][j] = t; }
        double ip = 1.0 / A[col][col];
        for (int r2 = col + 1; r2 < 6; r2++) {
            double f = A[r2][col] * ip;
            for (int j = col; j < 7; j++) A[r2][j] -= f * A[col][j];
        }
    }
    double x[6];
    for (int i = 5; i >= 0; i--) {
        double v = A[i][6];
        for (int j = i + 1; j < 6; j++) v -= A[i][j] * x[j];
        x[i] = v / A[i][i];
    }
    double delta[6];
    for (int i = 0; i < 6; i++) delta[i] = x[i] * jac[i];

    double w0 = delta[3], w1 = delta[4], w2 = delta[5];
    double th2 = w0 * w0 + w1 * w1 + w2 * w2;
    double th = sqrt(th2);
    double Ac, Bc;
    if (th < 1e-7) { Ac = 1.0; Bc = 0.5; }
    else           { Ac = sin(th) / th; Bc = (1.0 - cos(th)) / th2; }
    double Wm[9] = {0.0, -w2, w1, w2, 0.0, -w0, -w1, w0, 0.0};
    double W2[9];
    for (int i = 0; i < 3; i++)
        for (int j = 0; j < 3; j++) {
            double s2 = 0.0;
            for (int k = 0; k < 3; k++) s2 += Wm[i * 3 + k] * Wm[k * 3 + j];
            W2[i * 3 + j] = s2;
        }
    double dr[9];
    for (int i = 0; i < 9; i++) dr[i] = ((i % 4) == 0 ? 1.0 : 0.0) + Ac * Wm[i] + Bc * W2[i];

    double Rl[9], Tl[3];
    for (int i = 0; i < 9; i++) Rl[i] = g_R[i];
    for (int i = 0; i < 3; i++) Tl[i] = g_t[i];
    for (int i = 0; i < 3; i++) {
        for (int j = 0; j < 3; j++) {
            double s2 = 0.0;
            for (int k = 0; k < 3; k++) s2 += dr[i * 3 + k] * Rl[k * 3 + j];
            g_Rn[i * 3 + j] = s2;
        }
        g_tn[i] = dr[i * 3 + 0] * Tl[0] + dr[i * 3 + 1] * Tl[1] + dr[i * 3 + 2] * Tl[2] + delta[i];
    }
    for (int i = 0; i < 29; i++) g_acc[i] = 0.0;
    g_tacc[0] = 0.0;
    g_tacc[1] = 0.0;
}

// ---------------- trial cost ----------------
__global__ void __launch_bounds__(256) k_trial(const float* __restrict__ p3D,
                                               const float* __restrict__ fref,
                                               const float* __restrict__ Km, int N) {
    __shared__ double sh[2];
    int tid = threadIdx.x;
    if (tid < 2) sh[tid] = 0.0;
    __syncthreads();
    int lane = tid & 31, warp = tid >> 5;
    int wg = blockIdx.x * 8 + warp;
    int nw = gridDim.x * 8;
    float fx = Km[0], fy = Km[4], cx = Km[2], cy = Km[5];
    double R[9], T[3];
#pragma unroll
    for (int i = 0; i < 9; i++) R[i] = g_Rn[i];
#pragma unroll
    for (int i = 0; i < 3; i++) T[i] = g_tn[i];

    for (int pt = wg; pt < N; pt += nw) {
        float Px = p3D[3 * pt + 0], Py = p3D[3 * pt + 1], Pz = p3D[3 * pt + 2];
        double xd = R[0] * Px + R[1] * Py + R[2] * Pz + T[0];
        double yd = R[3] * Px + R[4] * Py + R[5] * Pz + T[1];
        double zd = R[6] * Px + R[7] * Py + R[8] * Pz + T[2];
        double izd = 1.0 / zd;
        float px = (float)(xd * izd * (double)fx + (double)cx);
        float py = (float)(yd * izd * (double)fy + (double)cy);
        if (!inImage(px, py)) continue;

        int o[4]; float w[4];
        bilin4(px, py, o, w);
        float acc[3] = {0.0f, 0.0f, 0.0f};  // n2, sdot, rn2
#pragma unroll
        for (int k = 0; k < 4; k++) {
            int c = lane + 32 * k;
            const float* B = g_fqT + c;
            float fb = w[0] * __ldg(B + o[0]) + w[1] * __ldg(B + o[1]) +
                       w[2] * __ldg(B + o[2]) + w[3] * __ldg(B + o[3]);
            float r = __ldg(fref + pt * NC + c);
            acc[0] += fb * fb;
            acc[1] += fb * r;
            acc[2] += r * r;
        }
        warpReduce<3>(acc);
        if (lane == 0) {
            double norm  = fmax(sqrt((double)acc[0]), 1e-12);
            double rnorm = fmax(sqrt((double)acc[2]), 1e-12);
            double errsq = (double)acc[0] / (norm * norm)
                         - 2.0 * (double)acc[1] / (norm * rnorm)
                         + (double)acc[2] / (rnorm * rnorm);
            atomicAdd(&sh[0], errsq);
            atomicAdd(&sh[1], 1.0);
        }
    }
    __syncthreads();
    if (tid < 2) atomicAdd(&g_tacc[tid], sh[tid]);
}

// ---------------- accept / reject ----------------
__global__ void k_accept() {
    double cn = g_tacc[0] / g_tacc[1];
    bool acc = (cn <= g_costbest);
    double l = g_lam * (acc ? 0.1 : 10.0);
    g_lam = fmin(fmax(l, 1e-8), 1e4);
    if (acc) {
        for (int i = 0; i < 9; i++) g_R[i] = g_Rn[i];
        for (int i = 0; i < 3; i++) g_t[i] = g_tn[i];
        g_costbest = cn;
    }
}

// ---------------- final costs + output ----------------
__global__ void __launch_bounds__(256) k_final(const float* __restrict__ p3D,
                                               const float* __restrict__ fref,
                                               const float* __restrict__ Km,
                                               int N, float* __restrict__ out) {
    int tid = threadIdx.x;
    int lane = tid & 31, warp = tid >> 5;
    int wg = blockIdx.x * 8 + warp;
    int nw = gridDim.x * 8;
    float fx = Km[0], fy = Km[4], cx = Km[2], cy = Km[5];
    double R[9], T[3];
#pragma unroll
    for (int i = 0; i < 9; i++) R[i] = g_R[i];
#pragma unroll
    for (int i = 0; i < 3; i++) T[i] = g_t[i];

    if (blockIdx.x == 0 && tid == 0) {
        for (int i = 0; i < 9; i++) out[i] = (float)R[i];
        for (int i = 0; i < 3; i++) out[9 + i] = (float)T[i];
    }
    const float NANF = __int_as_float(0x7fc00000);

    for (int pt = wg; pt < N; pt += nw) {
        float pix = g_p2init[2 * pt], piy = g_p2init[2 * pt + 1];
        float Px = p3D[3 * pt + 0], Py = p3D[3 * pt + 1], Pz = p3D[3 * pt + 2];
        double xd = R[0] * Px + R[1] * Py + R[2] * Pz + T[0];
        double yd = R[3] * Px + R[4] * Py + R[5] * Pz + T[1];
        double zd = R[6] * Px + R[7] * Py + R[8] * Pz + T[2];
        double izd = 1.0 / zd;
        float pfx = (float)(xd * izd * (double)fx + (double)cx);
        float pfy = (float)(yd * izd * (double)fy + (double)cy);

        int oi[4], of_[4];
        float wi[4], wf[4];
        bilin4(pix, piy, oi, wi);
        bilin4(pfx, pfy, of_, wf);

        float acc[5] = {0, 0, 0, 0, 0};  // n2i, si, n2f, sf, rn2
#pragma unroll
        for (int k = 0; k < 4; k++) {
            int c = lane + 32 * k;
            const float* B = g_fqT + c;
            float fi = wi[0] * __ldg(B + oi[0]) + wi[1] * __ldg(B + oi[1]) +
                       wi[2] * __ldg(B + oi[2]) + wi[3] * __ldg(B + oi[3]);
            float ff = wf[0] * __ldg(B + of_[0]) + wf[1] * __ldg(B + of_[1]) +
                       wf[2] * __ldg(B + of_[2]) + wf[3] * __ldg(B + of_[3]);
            float r = __ldg(fref + pt * NC + c);
            acc[0] += fi * fi; acc[1] += fi * r;
            acc[2] += ff * ff; acc[3] += ff * r;
            acc[4] += r * r;
        }
        warpReduce<5>(acc);
        if (lane == 0) {
            double rn = fmax(sqrt((double)acc[4]), 1e-12);
            double ni = fmax(sqrt((double)acc[0]), 1e-12);
            double nf = fmax(sqrt((double)acc[2]), 1e-12);
            double rr = (double)acc[4] / (rn * rn);
            double ci = rr - 2.0 * (double)acc[1] / (ni * rn) + (double)acc[0] / (ni * ni);
            double cf = rr - 2.0 * (double)acc[3] / (nf * rn) + (double)acc[2] / (nf * nf);
            out[12 + pt]     = inImage(pix, piy) ? (float)ci : NANF;
            out[12 + N + pt] = inImage(pfx, pfy) ? (float)cf : NANF;
        }
    }
}

// ---------------- launch ----------------
extern "C" void kernel_launch(void* const* d_in, const int* in_sizes, int n_in,
                              void* d_out, int out_size) {
    const float* p3D  = (const float*)d_in[0];
    const float* fref = (const float*)d_in[1];
    const float* fq   = (const float*)d_in[2];
    const float* Km   = (const float*)d_in[3];
    const float* R0   = (const float*)d_in[4];
    const float* t0   = (const float*)d_in[5];
    float* out = (float*)d_out;
    int N = in_sizes[0] / 3;
    if (N > MAXN) N = MAXN;

    k_init<<<1, 32>>>(R0, t0);
    k_transpose<<<NHW / 64, 256>>>(fq);
    for (int i = 0; i < 8; i++) {
        k_main<<<250, 256>>>(p3D, fref, Km, N, (i == 0) ? 1 : 0);
        k_solve<<<1, 1>>>(i);
        k_trial<<<250, 256>>>(p3D, fref, Km, N);
        k_accept<<<1, 1>>>();
    }
    k_final<<<313, 256>>>(p3D, fref, Km, N, out);
}

// round 2
// speedup vs baseline: 4.7802x; 4.7802x over previous
#include <cuda_runtime.h>
#include <math.h>

#define NC   128
#define WW   512
#define HH   512
#define NHW  (HH*WW)
#define MAXN 10000

// ---------------- persistent device state ----------------
__device__ __align__(256) float g_fqT[NC * NHW];  // (pixel, channel) layout
__device__ float  g_p2init[2 * MAXN];
__device__ double g_acc[29];    // [0..20] Hess uptri, [21..26] Grad, [27] cost, [28] count
__device__ double g_tacc[2];    // trial cost sum, count
__device__ double g_R[9], g_t[3], g_Rn[9], g_tn[3];
__device__ double g_lam, g_costbest, g_jac[6];

__constant__ int c_hi[21] = {0,0,0,0,0,0, 1,1,1,1,1, 2,2,2,2, 3,3,3, 4,4, 5};
__constant__ int c_hj[21] = {0,1,2,3,4,5, 1,2,3,4,5, 2,3,4,5, 3,4,5, 4,5, 5};

// ---------------- helpers ----------------
__device__ __forceinline__ float dot4(float4 a, float4 b) {
    return a.x * b.x + a.y * b.y + a.z * b.z + a.w * b.w;
}

template <int NV>
__device__ __forceinline__ void warpAllReduce(float* v) {
#pragma unroll
    for (int off = 16; off > 0; off >>= 1)
#pragma unroll
        for (int i = 0; i < NV; i++) v[i] += __shfl_xor_sync(0xffffffffu, v[i], off);
}

__device__ __forceinline__ float selJ0(int k, float fxz, float fxz2, float x, float y, float z) {
    switch (k) {
        case 0: return fxz;
        case 1: return 0.0f;
        case 2: return fxz2;
        case 3: return fxz2 * y;
        case 4: return fxz * z - fxz2 * x;
        default: return -fxz * y;
    }
}
__device__ __forceinline__ float selJ1(int k, float fyz, float fyz2, float x, float y, float z) {
    switch (k) {
        case 0: return 0.0f;
        case 1: return fyz;
        case 2: return fyz2;
        case 3: return -fyz * z + fyz2 * y;
        case 4: return -fyz2 * x;
        default: return fyz * x;
    }
}

__device__ __forceinline__ bool inImage(float px, float py) {
    return (px >= 1.0f) && (px < 511.0f) && (py >= 1.0f) && (py < 511.0f);
}

// bilinear footprint in float4 units (32 float4 per pixel)
__device__ __forceinline__ void bilin4(float px, float py, int* o, float* w) {
    float x0f = fminf(fmaxf(floorf(px), 0.0f), 511.0f);
    float y0f = fminf(fmaxf(floorf(py), 0.0f), 511.0f);
    float x1f = fminf(x0f + 1.0f, 511.0f);
    float y1f = fminf(y0f + 1.0f, 511.0f);
    float wx = px - x0f, wy = py - y0f;
    int x0 = (int)x0f, x1 = (int)x1f, y0 = (int)y0f, y1 = (int)y1f;
    o[0] = (y0 * WW + x0) * 32;
    o[1] = (y0 * WW + x1) * 32;
    o[2] = (y1 * WW + x0) * 32;
    o[3] = (y1 * WW + x1) * 32;
    w[0] = (1.0f - wx) * (1.0f - wy);
    w[1] = wx * (1.0f - wy);
    w[2] = (1.0f - wx) * wy;
    w[3] = wx * wy;
}

// ---------------- init ----------------
__global__ void k_init(const float* __restrict__ R0, const float* __restrict__ t0) {
    int i = threadIdx.x;
    if (i < 9) { g_R[i] = (double)R0[i]; g_Rn[i] = (double)R0[i]; }
    if (i < 3) { g_t[i] = (double)t0[i]; g_tn[i] = (double)t0[i]; }
    if (i == 0) { g_lam = 0.01; g_costbest = -1e300; g_tacc[0] = 0.0; g_tacc[1] = 1.0; }
    if (i < 29) g_acc[i] = 0.0;
}

// ---------------- transpose (C,H,W) -> (H*W, C) ----------------
__global__ void __launch_bounds__(256) k_transpose(const float* __restrict__ fq) {
    __shared__ float sh[64][NC + 1];
    int pix0 = blockIdx.x * 64;
    int tid = threadIdx.x;
    int px = tid & 63;
    int crow = tid >> 6;
#pragma unroll
    for (int cb = 0; cb < NC; cb += 4) {
        int c = cb + crow;
        sh[px][c] = fq[c * NHW + pix0 + px];
    }
    __syncthreads();
    int c2 = tid & 127;
    int prow = tid >> 7;
#pragma unroll
    for (int pb = 0; pb < 64; pb += 2) {
        int p = pb + prow;
        g_fqT[(pix0 + p) * NC + c2] = sh[p][c2];
    }
}

// ---------------- main LM accumulation ----------------
__global__ void __launch_bounds__(128) k_main(const float* __restrict__ p3D,
                                              const float* __restrict__ fref,
                                              const float* __restrict__ Km,
                                              int N, int isIter0) {
    int tid = threadIdx.x, lane = tid & 31, warp = tid >> 5;
    // local accept decision for previous trial (deterministic, matches k_solve commit)
    double cn = g_tacc[0] / g_tacc[1];
    bool accPrev = (cn <= g_costbest);
    float R[9], T[3];
#pragma unroll
    for (int i = 0; i < 9; i++) R[i] = (float)(accPrev ? g_Rn[i] : g_R[i]);
#pragma unroll
    for (int i = 0; i < 3; i++) T[i] = (float)(accPrev ? g_tn[i] : g_t[i]);
    float fx = Km[0], fy = Km[4], cx = Km[2], cy = Km[5];

    int hi = 0, hj = 0;
    if (lane < 21) { hi = c_hi[lane]; hj = c_hj[lane]; }
    else if (lane < 27) { hj = lane - 21; }

    double accD = 0.0;
    int wg = blockIdx.x * 4 + warp, nw = gridDim.x * 4;
    const float4* __restrict__ B4 = (const float4*)g_fqT;
    const float4* __restrict__ F4 = (const float4*)fref;

    for (int pt = wg; pt < N; pt += nw) {
        float Px = p3D[3 * pt], Py = p3D[3 * pt + 1], Pz = p3D[3 * pt + 2];
        float x_ = R[0] * Px + R[1] * Py + R[2] * Pz + T[0];
        float y_ = R[3] * Px + R[4] * Py + R[5] * Pz + T[1];
        float d  = R[6] * Px + R[7] * Py + R[8] * Pz + T[2];
        float izd = 1.0f / d;
        float px = x_ * izd * fx + cx;
        float py = y_ * izd * fy + cy;
        if (isIter0 && lane == 0) { g_p2init[2 * pt] = px; g_p2init[2 * pt + 1] = py; }
        if (!inImage(px, py)) continue;

        float x0f = fminf(fmaxf(floorf(px), 0.0f), 511.0f);
        float y0f = fminf(fmaxf(floorf(py), 0.0f), 511.0f);
        float x1f = fminf(x0f + 1.0f, 511.0f);
        float y1f = fminf(y0f + 1.0f, 511.0f);
        float wx = px - x0f, wy = py - y0f;
        int x0 = (int)x0f, x1 = (int)x1f, y0 = (int)y0f, y1 = (int)y1f;
        int colo[4] = {(x0 > 0 ? x0 - 1 : 0) * 32, x0 * 32, x1 * 32,
                       (x1 < 511 ? x1 + 1 : 511) * 32};
        int rowo[4] = {(y0 > 0 ? y0 - 1 : 0) * (WW * 32), y0 * (WW * 32), y1 * (WW * 32),
                       (y1 < 511 ? y1 + 1 : 511) * (WW * 32)};
        float w00 = (1.0f - wx) * (1.0f - wy), w01 = wx * (1.0f - wy);
        float w10 = (1.0f - wx) * wy,          w11 = wx * wy;

        // combined (bilinear x sobel) weights over the 4x4 patch
        float wgx[16], wgy[16];
#pragma unroll
        for (int k = 0; k < 16; k++) { wgx[k] = 0.0f; wgy[k] = 0.0f; }
        const float KX[3][3] = {{-0.125f, 0.0f, 0.125f}, {-0.25f, 0.0f, 0.25f}, {-0.125f, 0.0f, 0.125f}};
        const float KY[3][3] = {{-0.125f, -0.25f, -0.125f}, {0.0f, 0.0f, 0.0f}, {0.125f, 0.25f, 0.125f}};
        float wb[2][2] = {{w00, w01}, {w10, w11}};
#pragma unroll
        for (int a = 0; a < 2; a++)
#pragma unroll
            for (int b = 0; b < 2; b++) {
                float wc = wb[a][b];
#pragma unroll
                for (int u = 0; u < 3; u++)
#pragma unroll
                    for (int v = 0; v < 3; v++) {
                        wgx[(a + u) * 4 + (b + v)] += wc * KX[u][v];
                        wgy[(a + u) * 4 + (b + v)] += wc * KY[u][v];
                    }
            }

        float4 f4  = make_float4(0, 0, 0, 0);
        float4 gx4 = make_float4(0, 0, 0, 0);
        float4 gy4 = make_float4(0, 0, 0, 0);
#pragma unroll
        for (int k = 0; k < 16; k++) {
            float4 p = __ldg(&B4[rowo[k >> 2] + colo[k & 3] + lane]);
            gx4.x += wgx[k] * p.x; gx4.y += wgx[k] * p.y; gx4.z += wgx[k] * p.z; gx4.w += wgx[k] * p.w;
            gy4.x += wgy[k] * p.x; gy4.y += wgy[k] * p.y; gy4.z += wgy[k] * p.z; gy4.w += wgy[k] * p.w;
            if (k == 5 || k == 6 || k == 9 || k == 10) {
                float wf = (k == 5) ? w00 : (k == 6) ? w01 : (k == 9) ? w10 : w11;
                f4.x += wf * p.x; f4.y += wf * p.y; f4.z += wf * p.z; f4.w += wf * p.w;
            }
        }
        float4 r4 = __ldg(&F4[pt * 32 + lane]);

        float s[10];
        s[0] = dot4(f4, f4);   s[1] = dot4(f4, gx4);  s[2] = dot4(f4, gy4);
        s[3] = dot4(gx4, gx4); s[4] = dot4(gx4, gy4); s[5] = dot4(gy4, gy4);
        s[6] = dot4(gx4, r4);  s[7] = dot4(gy4, r4);  s[8] = dot4(f4, r4);
        s[9] = dot4(r4, r4);
        warpAllReduce<10>(s);

        float norm  = fmaxf(sqrtf(s[0]), 1e-12f);
        float rnorm = fmaxf(sqrtf(s[9]), 1e-12f);
        float inorm = 1.0f / norm, irn = 1.0f / rnorm;
        float projx = s[1] * inorm, projy = s[2] * inorm;
        float nf2 = s[0] * inorm * inorm;
        float sc  = s[8] * inorm * irn;
        float in2 = inorm * inorm;
        float fac = 2.0f - nf2;
        float Mxx = (s[3] - projx * projx * fac) * in2;
        float Mxy = (s[4] - projx * projy * fac) * in2;
        float Myy = (s[5] - projy * projy * fac) * in2;
        float coef = 1.0f - nf2 + sc;
        float g2x = (projx * coef - s[6] * irn) * inorm;
        float g2y = (projy * coef - s[7] * irn) * inorm;

        float fxz = fx * izd, fxz2 = -fx * x_ * izd * izd;
        float fyz = fy * izd, fyz2 = -fy * y_ * izd * izd;

        float val;
        if (lane < 21) {
            float a0 = selJ0(hi, fxz, fxz2, x_, y_, d);
            float a1 = selJ1(hi, fyz, fyz2, x_, y_, d);
            float b0 = selJ0(hj, fxz, fxz2, x_, y_, d);
            float b1 = selJ1(hj, fyz, fyz2, x_, y_, d);
            float u  = Mxx * a0 + Mxy * a1;
            float vv = Mxy * a0 + Myy * a1;
            val = u * b0 + vv * b1;
        } else if (lane < 27) {
            float b0 = selJ0(hj, fxz, fxz2, x_, y_, d);
            float b1 = selJ1(hj, fyz, fyz2, x_, y_, d);
            val = g2x * b0 + g2y * b1;
        } else if (lane == 27) {
            val = nf2 - 2.0f * sc + s[9] * irn * irn;
        } else if (lane == 28) {
            val = 1.0f;
        } else {
            val = 0.0f;
        }
        accD += (double)val;
    }

    __shared__ double sred[4][29];
    if (lane < 29) sred[warp][lane] = accD;
    __syncthreads();
    if (warp == 0 && lane < 29) {
        double t2 = sred[0][lane] + sred[1][lane] + sred[2][lane] + sred[3][lane];
        atomicAdd(&g_acc[lane], t2);
    }
}

// ---------------- solve: commit prev accept + jacobi + 6x6 GE + SO3 ----------------
__global__ void k_solve(int iter) {
    int lane = threadIdx.x;
    __shared__ double sA[6][8];
    __shared__ double sv[8];
    __shared__ int s_piv;
    __shared__ double sdelta[6];

    double accv = (lane < 29) ? g_acc[lane] : 0.0;

    if (lane == 0) {
        if (iter > 0) {
            double cn = g_tacc[0] / g_tacc[1];
            bool a = (cn <= g_costbest);
            double l = g_lam * (a ? 0.1 : 10.0);
            g_lam = fmin(fmax(l, 1e-8), 1e4);
            if (a) {
#pragma unroll
                for (int i = 0; i < 9; i++) g_R[i] = g_Rn[i];
#pragma unroll
                for (int i = 0; i < 3; i++) g_t[i] = g_tn[i];
                g_costbest = cn;
            }
        } else {
            g_costbest = g_acc[27] / g_acc[28];
        }
    }
    __syncwarp();
    if (iter == 0 && lane < 6) {
        const int dix[6] = {0, 6, 11, 15, 18, 20};
        g_jac[lane] = 1.0 / (1.0 + sqrt(g_acc[dix[lane]]));
    }
    __syncwarp();
    if (lane < 21) {
        int i = c_hi[lane], j = c_hj[lane];
        double v = accv * g_jac[i] * g_jac[j];
        sA[i][j] = v;
        sA[j][i] = v;
    }
    __syncwarp();
    double lam = g_lam;
    if (lane < 6) {
        double dgd = sA[lane][lane];
        sA[lane][lane] = dgd + (dgd + 1e-9) * lam;
        sA[lane][6] = -g_acc[21 + lane] * g_jac[lane];
    }
    __syncwarp();
    // Gaussian elimination with partial pivoting
    for (int col = 0; col < 6; col++) {
        if (lane == 0) {
            int piv = col;
            double best = fabs(sA[col][col]);
            for (int r2 = col + 1; r2 < 6; r2++) {
                double v = fabs(sA[r2][col]);
                if (v > best) { best = v; piv = r2; }
            }
            s_piv = piv;
        }
        __syncwarp();
        int piv = s_piv;
        if (piv != col && lane < 7) {
            double tv = sA[col][lane];
            sA[col][lane] = sA[piv][lane];
            sA[piv][lane] = tv;
        }
        __syncwarp();
        if (lane < 6 && lane > col) sv[lane] = sA[lane][col] / sA[col][col];
        __syncwarp();
        {
            int nrow = 5 - col;
            int idx = lane;
            if (idx < nrow * 7) {
                int r = col + 1 + idx / 7, j = idx % 7;
                sA[r][j] -= sv[r] * sA[col][j];
            }
            idx = lane + 32;
            if (idx < nrow * 7) {
                int r = col + 1 + idx / 7, j = idx % 7;
                sA[r][j] -= sv[r] * sA[col][j];
            }
        }
        __syncwarp();
    }
    if (lane == 0) {
        double x[6];
#pragma unroll
        for (int i = 5; i >= 0; i--) {
            double v = sA[i][6];
#pragma unroll
            for (int j = 0; j < 6; j++)
                if (j > i) v -= sA[i][j] * x[j];
            x[i] = v / sA[i][i];
        }
#pragma unroll
        for (int i = 0; i < 6; i++) sdelta[i] = x[i] * g_jac[i];
    }
    __syncwarp();
    if (lane == 0) {
        double w0 = sdelta[3], w1 = sdelta[4], w2 = sdelta[5];
        double th2 = w0 * w0 + w1 * w1 + w2 * w2;
        double th = sqrt(th2);
        double Ac, Bc;
        if (th < 1e-7) { Ac = 1.0; Bc = 0.5; }
        else           { Ac = sin(th) / th; Bc = (1.0 - cos(th)) / th2; }
        double Wm[9] = {0.0, -w2, w1, w2, 0.0, -w0, -w1, w0, 0.0};
        double W2[9];
#pragma unroll
        for (int i = 0; i < 3; i++)
#pragma unroll
            for (int j = 0; j < 3; j++) {
                double s2 = 0.0;
#pragma unroll
                for (int k = 0; k < 3; k++) s2 += Wm[i * 3 + k] * Wm[k * 3 + j];
                W2[i * 3 + j] = s2;
            }
        double dr[9];
#pragma unroll
        for (int i = 0; i < 9; i++)
            dr[i] = ((i % 4) == 0 ? 1.0 : 0.0) + Ac * Wm[i] + Bc * W2[i];
        double Rl[9], Tl[3];
#pragma unroll
        for (int i = 0; i < 9; i++) Rl[i] = g_R[i];
#pragma unroll
        for (int i = 0; i < 3; i++) Tl[i] = g_t[i];
#pragma unroll
        for (int i = 0; i < 3; i++) {
#pragma unroll
            for (int j = 0; j < 3; j++) {
                double s2 = 0.0;
#pragma unroll
                for (int k = 0; k < 3; k++) s2 += dr[i * 3 + k] * Rl[k * 3 + j];
                g_Rn[i * 3 + j] = s2;
            }
            g_tn[i] = dr[i * 3] * Tl[0] + dr[i * 3 + 1] * Tl[1] + dr[i * 3 + 2] * Tl[2] + sdelta[i];
        }
    }
    __syncwarp();
    if (lane < 29) g_acc[lane] = 0.0;
    if (lane < 2)  g_tacc[lane] = 0.0;
}

// ---------------- trial cost for candidate pose ----------------
__global__ void __launch_bounds__(128) k_trial(const float* __restrict__ p3D,
                                               const float* __restrict__ fref,
                                               const float* __restrict__ Km, int N) {
    int tid = threadIdx.x, lane = tid & 31, warp = tid >> 5;
    float R[9], T[3];
#pragma unroll
    for (int i = 0; i < 9; i++) R[i] = (float)g_Rn[i];
#pragma unroll
    for (int i = 0; i < 3; i++) T[i] = (float)g_tn[i];
    float fx = Km[0], fy = Km[4], cx = Km[2], cy = Km[5];

    double cD = 0.0, cC = 0.0;
    int wg = blockIdx.x * 4 + warp, nw = gridDim.x * 4;
    const float4* __restrict__ B4 = (const float4*)g_fqT;
    const float4* __restrict__ F4 = (const float4*)fref;

    for (int pt = wg; pt < N; pt += nw) {
        float Px = p3D[3 * pt], Py = p3D[3 * pt + 1], Pz = p3D[3 * pt + 2];
        float x_ = R[0] * Px + R[1] * Py + R[2] * Pz + T[0];
        float y_ = R[3] * Px + R[4] * Py + R[5] * Pz + T[1];
        float d  = R[6] * Px + R[7] * Py + R[8] * Pz + T[2];
        float izd = 1.0f / d;
        float px = x_ * izd * fx + cx;
        float py = y_ * izd * fy + cy;
        if (!inImage(px, py)) continue;

        int o[4]; float w[4];
        bilin4(px, py, o, w);
        float4 f4 = make_float4(0, 0, 0, 0);
#pragma unroll
        for (int k = 0; k < 4; k++) {
            float4 p = __ldg(&B4[o[k] + lane]);
            f4.x += w[k] * p.x; f4.y += w[k] * p.y; f4.z += w[k] * p.z; f4.w += w[k] * p.w;
        }
        float4 r4 = __ldg(&F4[pt * 32 + lane]);
        float s[3];
        s[0] = dot4(f4, f4);
        s[1] = dot4(f4, r4);
        s[2] = dot4(r4, r4);
        warpAllReduce<3>(s);
        if (lane == 0) {
            float inorm = 1.0f / fmaxf(sqrtf(s[0]), 1e-12f);
            float irn   = 1.0f / fmaxf(sqrtf(s[2]), 1e-12f);
            float errsq = s[0] * inorm * inorm - 2.0f * s[1] * inorm * irn + s[2] * irn * irn;
            cD += (double)errsq;
            cC += 1.0;
        }
    }
    __shared__ double sD[4], sC[4];
    if (lane == 0) { sD[warp] = cD; sC[warp] = cC; }
    __syncthreads();
    if (tid == 0) {
        atomicAdd(&g_tacc[0], sD[0] + sD[1] + sD[2] + sD[3]);
        atomicAdd(&g_tacc[1], sC[0] + sC[1] + sC[2] + sC[3]);
    }
}

// ---------------- final costs + output ----------------
__global__ void __launch_bounds__(128) k_final(const float* __restrict__ p3D,
                                               const float* __restrict__ fref,
                                               const float* __restrict__ Km,
                                               int N, float* __restrict__ out) {
    int tid = threadIdx.x, lane = tid & 31, warp = tid >> 5;
    double cn = g_tacc[0] / g_tacc[1];
    bool accPrev = (cn <= g_costbest);
    float R[9], T[3];
#pragma unroll
    for (int i = 0; i < 9; i++) R[i] = (float)(accPrev ? g_Rn[i] : g_R[i]);
#pragma unroll
    for (int i = 0; i < 3; i++) T[i] = (float)(accPrev ? g_tn[i] : g_t[i]);
    float fx = Km[0], fy = Km[4], cx = Km[2], cy = Km[5];

    if (blockIdx.x == 0 && tid == 0) {
#pragma unroll
        for (int i = 0; i < 9; i++) out[i] = (float)(accPrev ? g_Rn[i] : g_R[i]);
#pragma unroll
        for (int i = 0; i < 3; i++) out[9 + i] = (float)(accPrev ? g_tn[i] : g_t[i]);
    }
    const float NANF = __int_as_float(0x7fc00000);

    int wg = blockIdx.x * 4 + warp, nw = gridDim.x * 4;
    const float4* __restrict__ B4 = (const float4*)g_fqT;
    const float4* __restrict__ F4 = (const float4*)fref;

    for (int pt = wg; pt < N; pt += nw) {
        float pix = g_p2init[2 * pt], piy = g_p2init[2 * pt + 1];
        float Px = p3D[3 * pt], Py = p3D[3 * pt + 1], Pz = p3D[3 * pt + 2];
        float x_ = R[0] * Px + R[1] * Py + R[2] * Pz + T[0];
        float y_ = R[3] * Px + R[4] * Py + R[5] * Pz + T[1];
        float d  = R[6] * Px + R[7] * Py + R[8] * Pz + T[2];
        float izd = 1.0f / d;
        float pfx = x_ * izd * fx + cx;
        float pfy = y_ * izd * fy + cy;

        int oi[4], of_[4];
        float wi[4], wf[4];
        bilin4(pix, piy, oi, wi);
        bilin4(pfx, pfy, of_, wf);

        float4 fi4 = make_float4(0, 0, 0, 0);
        float4 ff4 = make_float4(0, 0, 0, 0);
#pragma unroll
        for (int k = 0; k < 4; k++) {
            float4 pi = __ldg(&B4[oi[k] + lane]);
            float4 pf = __ldg(&B4[of_[k] + lane]);
            fi4.x += wi[k] * pi.x; fi4.y += wi[k] * pi.y; fi4.z += wi[k] * pi.z; fi4.w += wi[k] * pi.w;
            ff4.x += wf[k] * pf.x; ff4.y += wf[k] * pf.y; ff4.z += wf[k] * pf.z; ff4.w += wf[k] * pf.w;
        }
        float4 r4 = __ldg(&F4[pt * 32 + lane]);
        float s[5];
        s[0] = dot4(fi4, fi4);
        s[1] = dot4(fi4, r4);
        s[2] = dot4(ff4, ff4);
        s[3] = dot4(ff4, r4);
        s[4] = dot4(r4, r4);
        warpAllReduce<5>(s);
        if (lane == 0) {
            float irn = 1.0f / fmaxf(sqrtf(s[4]), 1e-12f);
            float ini = 1.0f / fmaxf(sqrtf(s[0]), 1e-12f);
            float inf_ = 1.0f / fmaxf(sqrtf(s[2]), 1e-12f);
            float rr = s[4] * irn * irn;
            float ci = rr - 2.0f * s[1] * ini * irn + s[0] * ini * ini;
            float cf = rr - 2.0f * s[3] * inf_ * irn + s[2] * inf_ * inf_;
            out[12 + pt]     = inImage(pix, piy) ? ci : NANF;
            out[12 + N + pt] = inImage(pfx, pfy) ? cf : NANF;
        }
    }
}

// ---------------- launch ----------------
extern "C" void kernel_launch(void* const* d_in, const int* in_sizes, int n_in,
                              void* d_out, int out_size) {
    const float* p3D  = (const float*)d_in[0];
    const float* fref = (const float*)d_in[1];
    const float* fq   = (const float*)d_in[2];
    const float* Km   = (const float*)d_in[3];
    const float* R0   = (const float*)d_in[4];
    const float* t0   = (const float*)d_in[5];
    float* out = (float*)d_out;
    int N = in_sizes[0] / 3;
    if (N > MAXN) N = MAXN;

    k_init<<<1, 32>>>(R0, t0);
    k_transpose<<<NHW / 64, 256>>>(fq);
    for (int i = 0; i < 8; i++) {
        k_main<<<500, 128>>>(p3D, fref, Km, N, (i == 0) ? 1 : 0);
        k_solve<<<1, 32>>>(i);
        k_trial<<<500, 128>>>(p3D, fref, Km, N);
    }
    k_final<<<500, 128>>>(p3D, fref, Km, N, out);
}

// round 3
// speedup vs baseline: 4.8005x; 1.0042x over previous
#include <cuda_runtime.h>
#include <math.h>

#define NC   128
#define WW   512
#define HH   512
#define NHW  (HH*WW)
#define MAXN 10000

// ---------------- persistent device state ----------------
__device__ __align__(256) float g_fqT[NC * NHW];  // (pixel, channel) layout
__device__ float  g_p2init[2 * MAXN];
__device__ double g_acc[29];    // [0..20] Hess uptri, [21..26] Grad, [27] cost, [28] count
__device__ double g_tacc[2];    // trial cost sum, count
__device__ double g_R[9], g_t[3], g_Rn[9], g_tn[3];
__device__ double g_lam, g_costbest, g_jac[6];

__constant__ int c_hi[21] = {0,0,0,0,0,0, 1,1,1,1,1, 2,2,2,2, 3,3,3, 4,4, 5};
__constant__ int c_hj[21] = {0,1,2,3,4,5, 1,2,3,4,5, 2,3,4,5, 3,4,5, 4,5, 5};

// ---------------- helpers ----------------
__device__ __forceinline__ float dot4(float4 a, float4 b) {
    return a.x * b.x + a.y * b.y + a.z * b.z + a.w * b.w;
}

template <int NV>
__device__ __forceinline__ void warpAllReduce(float* v) {
#pragma unroll
    for (int off = 16; off > 0; off >>= 1)
#pragma unroll
        for (int i = 0; i < NV; i++) v[i] += __shfl_xor_sync(0xffffffffu, v[i], off);
}

__device__ __forceinline__ float selJ0(int k, float fxz, float fxz2, float x, float y, float z) {
    switch (k) {
        case 0: return fxz;
        case 1: return 0.0f;
        case 2: return fxz2;
        case 3: return fxz2 * y;
        case 4: return fxz * z - fxz2 * x;
        default: return -fxz * y;
    }
}
__device__ __forceinline__ float selJ1(int k, float fyz, float fyz2, float x, float y, float z) {
    switch (k) {
        case 0: return 0.0f;
        case 1: return fyz;
        case 2: return fyz2;
        case 3: return -fyz * z + fyz2 * y;
        case 4: return -fyz2 * x;
        default: return fyz * x;
    }
}

__device__ __forceinline__ bool inImage(float px, float py) {
    return (px >= 1.0f) && (px < 511.0f) && (py >= 1.0f) && (py < 511.0f);
}

// bilinear footprint in float4 units (32 float4 per pixel)
__device__ __forceinline__ void bilin4(float px, float py, int* o, float* w) {
    float x0f = fminf(fmaxf(floorf(px), 0.0f), 511.0f);
    float y0f = fminf(fmaxf(floorf(py), 0.0f), 511.0f);
    float x1f = fminf(x0f + 1.0f, 511.0f);
    float y1f = fminf(y0f + 1.0f, 511.0f);
    float wx = px - x0f, wy = py - y0f;
    int x0 = (int)x0f, x1 = (int)x1f, y0 = (int)y0f, y1 = (int)y1f;
    o[0] = (y0 * WW + x0) * 32;
    o[1] = (y0 * WW + x1) * 32;
    o[2] = (y1 * WW + x0) * 32;
    o[3] = (y1 * WW + x1) * 32;
    w[0] = (1.0f - wx) * (1.0f - wy);
    w[1] = wx * (1.0f - wy);
    w[2] = (1.0f - wx) * wy;
    w[3] = wx * wy;
}

// ---------------- init ----------------
__global__ void k_init(const float* __restrict__ R0, const float* __restrict__ t0) {
    int i = threadIdx.x;
    if (i < 9) { g_R[i] = (double)R0[i]; g_Rn[i] = (double)R0[i]; }
    if (i < 3) { g_t[i] = (double)t0[i]; g_tn[i] = (double)t0[i]; }
    if (i == 0) { g_lam = 0.01; g_costbest = -1e300; g_tacc[0] = 0.0; g_tacc[1] = 1.0; }
    if (i < 29) g_acc[i] = 0.0;
}

// ---------------- transpose (C,H,W) -> (H*W, C) ----------------
__global__ void __launch_bounds__(256) k_transpose(const float* __restrict__ fq) {
    __shared__ float sh[64][NC + 1];
    int pix0 = blockIdx.x * 64;
    int tid = threadIdx.x;
    int px = tid & 63;
    int crow = tid >> 6;
#pragma unroll
    for (int cb = 0; cb < NC; cb += 4) {
        int c = cb + crow;
        sh[px][c] = fq[c * NHW + pix0 + px];
    }
    __syncthreads();
    int c2 = tid & 127;
    int prow = tid >> 7;
#pragma unroll
    for (int pb = 0; pb < 64; pb += 2) {
        int p = pb + prow;
        g_fqT[(pix0 + p) * NC + c2] = sh[p][c2];
    }
}

// ---------------- main LM accumulation ----------------
__global__ void __launch_bounds__(128) k_main(const float* __restrict__ p3D,
                                              const float* __restrict__ fref,
                                              const float* __restrict__ Km,
                                              int N, int isIter0) {
    int tid = threadIdx.x, lane = tid & 31, warp = tid >> 5;
    // local accept decision for previous trial (deterministic, matches k_solve commit)
    double cn = g_tacc[0] / g_tacc[1];
    bool accPrev = (cn <= g_costbest);
    float R[9], T[3];
#pragma unroll
    for (int i = 0; i < 9; i++) R[i] = (float)(accPrev ? g_Rn[i] : g_R[i]);
#pragma unroll
    for (int i = 0; i < 3; i++) T[i] = (float)(accPrev ? g_tn[i] : g_t[i]);
    float fx = Km[0], fy = Km[4], cx = Km[2], cy = Km[5];

    int hi = 0, hj = 0;
    if (lane < 21) { hi = c_hi[lane]; hj = c_hj[lane]; }
    else if (lane < 27) { hj = lane - 21; }

    double accD = 0.0;
    int wg = blockIdx.x * 4 + warp, nw = gridDim.x * 4;
    const float4* __restrict__ B4 = (const float4*)g_fqT;
    const float4* __restrict__ F4 = (const float4*)fref;

    for (int pt = wg; pt < N; pt += nw) {
        float Px = p3D[3 * pt], Py = p3D[3 * pt + 1], Pz = p3D[3 * pt + 2];
        float x_ = R[0] * Px + R[1] * Py + R[2] * Pz + T[0];
        float y_ = R[3] * Px + R[4] * Py + R[5] * Pz + T[1];
        float d  = R[6] * Px + R[7] * Py + R[8] * Pz + T[2];
        float izd = 1.0f / d;
        float px = x_ * izd * fx + cx;
        float py = y_ * izd * fy + cy;
        if (isIter0 && lane == 0) { g_p2init[2 * pt] = px; g_p2init[2 * pt + 1] = py; }
        if (!inImage(px, py)) continue;

        float x0f = fminf(fmaxf(floorf(px), 0.0f), 511.0f);
        float y0f = fminf(fmaxf(floorf(py), 0.0f), 511.0f);
        float x1f = fminf(x0f + 1.0f, 511.0f);
        float y1f = fminf(y0f + 1.0f, 511.0f);
        float wx = px - x0f, wy = py - y0f;
        int x0 = (int)x0f, x1 = (int)x1f, y0 = (int)y0f, y1 = (int)y1f;
        int colo[4] = {(x0 > 0 ? x0 - 1 : 0) * 32, x0 * 32, x1 * 32,
                       (x1 < 511 ? x1 + 1 : 511) * 32};
        int rowo[4] = {(y0 > 0 ? y0 - 1 : 0) * (WW * 32), y0 * (WW * 32), y1 * (WW * 32),
                       (y1 < 511 ? y1 + 1 : 511) * (WW * 32)};
        float w00 = (1.0f - wx) * (1.0f - wy), w01 = wx * (1.0f - wy);
        float w10 = (1.0f - wx) * wy,          w11 = wx * wy;

        // combined (bilinear x sobel) weights over the 4x4 patch
        float wgx[16], wgy[16];
#pragma unroll
        for (int k = 0; k < 16; k++) { wgx[k] = 0.0f; wgy[k] = 0.0f; }
        const float KX[3][3] = {{-0.125f, 0.0f, 0.125f}, {-0.25f, 0.0f, 0.25f}, {-0.125f, 0.0f, 0.125f}};
        const float KY[3][3] = {{-0.125f, -0.25f, -0.125f}, {0.0f, 0.0f, 0.0f}, {0.125f, 0.25f, 0.125f}};
        float wb[2][2] = {{w00, w01}, {w10, w11}};
#pragma unroll
        for (int a = 0; a < 2; a++)
#pragma unroll
            for (int b = 0; b < 2; b++) {
                float wc = wb[a][b];
#pragma unroll
                for (int u = 0; u < 3; u++)
#pragma unroll
                    for (int v = 0; v < 3; v++) {
                        wgx[(a + u) * 4 + (b + v)] += wc * KX[u][v];
                        wgy[(a + u) * 4 + (b + v)] += wc * KY[u][v];
                    }
            }

        float4 f4  = make_float4(0, 0, 0, 0);
        float4 gx4 = make_float4(0, 0, 0, 0);
        float4 gy4 = make_float4(0, 0, 0, 0);
#pragma unroll
        for (int k = 0; k < 16; k++) {
            float4 p = __ldg(&B4[rowo[k >> 2] + colo[k & 3] + lane]);
            gx4.x += wgx[k] * p.x; gx4.y += wgx[k] * p.y; gx4.z += wgx[k] * p.z; gx4.w += wgx[k] * p.w;
            gy4.x += wgy[k] * p.x; gy4.y += wgy[k] * p.y; gy4.z += wgy[k] * p.z; gy4.w += wgy[k] * p.w;
            if (k == 5 || k == 6 || k == 9 || k == 10) {
                float wf = (k == 5) ? w00 : (k == 6) ? w01 : (k == 9) ? w10 : w11;
                f4.x += wf * p.x; f4.y += wf * p.y; f4.z += wf * p.z; f4.w += wf * p.w;
            }
        }
        float4 r4 = __ldg(&F4[pt * 32 + lane]);

        float s[10];
        s[0] = dot4(f4, f4);   s[1] = dot4(f4, gx4);  s[2] = dot4(f4, gy4);
        s[3] = dot4(gx4, gx4); s[4] = dot4(gx4, gy4); s[5] = dot4(gy4, gy4);
        s[6] = dot4(gx4, r4);  s[7] = dot4(gy4, r4);  s[8] = dot4(f4, r4);
        s[9] = dot4(r4, r4);
        warpAllReduce<10>(s);

        float norm  = fmaxf(sqrtf(s[0]), 1e-12f);
        float rnorm = fmaxf(sqrtf(s[9]), 1e-12f);
        float inorm = 1.0f / norm, irn = 1.0f / rnorm;
        float projx = s[1] * inorm, projy = s[2] * inorm;
        float nf2 = s[0] * inorm * inorm;
        float sc  = s[8] * inorm * irn;
        float in2 = inorm * inorm;
        float fac = 2.0f - nf2;
        float Mxx = (s[3] - projx * projx * fac) * in2;
        float Mxy = (s[4] - projx * projy * fac) * in2;
        float Myy = (s[5] - projy * projy * fac) * in2;
        float coef = 1.0f - nf2 + sc;
        float g2x = (projx * coef - s[6] * irn) * inorm;
        float g2y = (projy * coef - s[7] * irn) * inorm;

        float fxz = fx * izd, fxz2 = -fx * x_ * izd * izd;
        float fyz = fy * izd, fyz2 = -fy * y_ * izd * izd;

        float val;
        if (lane < 21) {
            float a0 = selJ0(hi, fxz, fxz2, x_, y_, d);
            float a1 = selJ1(hi, fyz, fyz2, x_, y_, d);
            float b0 = selJ0(hj, fxz, fxz2, x_, y_, d);
            float b1 = selJ1(hj, fyz, fyz2, x_, y_, d);
            float u  = Mxx * a0 + Mxy * a1;
            float vv = Mxy * a0 + Myy * a1;
            val = u * b0 + vv * b1;
        } else if (lane < 27) {
            float b0 = selJ0(hj, fxz, fxz2, x_, y_, d);
            float b1 = selJ1(hj, fyz, fyz2, x_, y_, d);
            val = g2x * b0 + g2y * b1;
        } else if (lane == 27) {
            val = nf2 - 2.0f * sc + s[9] * irn * irn;
        } else if (lane == 28) {
            val = 1.0f;
        } else {
            val = 0.0f;
        }
        accD += (double)val;
    }

    __shared__ double sred[4][29];
    if (lane < 29) sred[warp][lane] = accD;
    __syncthreads();
    if (warp == 0 && lane < 29) {
        double t2 = sred[0][lane] + sred[1][lane] + sred[2][lane] + sred[3][lane];
        atomicAdd(&g_acc[lane], t2);
    }
}

// ---------------- solve: commit prev accept + jacobi + 6x6 GE + SO3 ----------------
__global__ void k_solve(int iter) {
    int lane = threadIdx.x;
    __shared__ double sA[6][8];
    __shared__ double sv[8];
    __shared__ int s_piv;
    __shared__ double sdelta[6];

    double accv = (lane < 29) ? g_acc[lane] : 0.0;

    if (lane == 0) {
        if (iter > 0) {
            double cn = g_tacc[0] / g_tacc[1];
            bool a = (cn <= g_costbest);
            double l = g_lam * (a ? 0.1 : 10.0);
            g_lam = fmin(fmax(l, 1e-8), 1e4);
            if (a) {
#pragma unroll
                for (int i = 0; i < 9; i++) g_R[i] = g_Rn[i];
#pragma unroll
                for (int i = 0; i < 3; i++) g_t[i] = g_tn[i];
                g_costbest = cn;
            }
        } else {
            g_costbest = g_acc[27] / g_acc[28];
        }
    }
    __syncwarp();
    if (iter == 0 && lane < 6) {
        const int dix[6] = {0, 6, 11, 15, 18, 20};
        g_jac[lane] = 1.0 / (1.0 + sqrt(g_acc[dix[lane]]));
    }
    __syncwarp();
    if (lane < 21) {
        int i = c_hi[lane], j = c_hj[lane];
        double v = accv * g_jac[i] * g_jac[j];
        sA[i][j] = v;
        sA[j][i] = v;
    }
    __syncwarp();
    double lam = g_lam;
    if (lane < 6) {
        double dgd = sA[lane][lane];
        sA[lane][lane] = dgd + (dgd + 1e-9) * lam;
        sA[lane][6] = -g_acc[21 + lane] * g_jac[lane];
    }
    __syncwarp();
    // Gaussian elimination with partial pivoting
    for (int col = 0; col < 6; col++) {
        if (lane == 0) {
            int piv = col;
            double best = fabs(sA[col][col]);
            for (int r2 = col + 1; r2 < 6; r2++) {
                double v = fabs(sA[r2][col]);
                if (v > best) { best = v; piv = r2; }
            }
            s_piv = piv;
        }
        __syncwarp();
        int piv = s_piv;
        if (piv != col && lane < 7) {
            double tv = sA[col][lane];
            sA[col][lane] = sA[piv][lane];
            sA[piv][lane] = tv;
        }
        __syncwarp();
        if (lane < 6 && lane > col) sv[lane] = sA[lane][col] / sA[col][col];
        __syncwarp();
        {
            int nrow = 5 - col;
            int idx = lane;
            if (idx < nrow * 7) {
                int r = col + 1 + idx / 7, j = idx % 7;
                sA[r][j] -= sv[r] * sA[col][j];
            }
            idx = lane + 32;
            if (idx < nrow * 7) {
                int r = col + 1 + idx / 7, j = idx % 7;
                sA[r][j] -= sv[r] * sA[col][j];
            }
        }
        __syncwarp();
    }
    if (lane == 0) {
        double x[6];
#pragma unroll
        for (int i = 5; i >= 0; i--) {
            double v = sA[i][6];
#pragma unroll
            for (int j = 0; j < 6; j++)
                if (j > i) v -= sA[i][j] * x[j];
            x[i] = v / sA[i][i];
        }
#pragma unroll
        for (int i = 0; i < 6; i++) sdelta[i] = x[i] * g_jac[i];
    }
    __syncwarp();
    if (lane == 0) {
        double w0 = sdelta[3], w1 = sdelta[4], w2 = sdelta[5];
        double th2 = w0 * w0 + w1 * w1 + w2 * w2;
        double th = sqrt(th2);
        double Ac, Bc;
        if (th < 1e-7) { Ac = 1.0; Bc = 0.5; }
        else           { Ac = sin(th) / th; Bc = (1.0 - cos(th)) / th2; }
        double Wm[9] = {0.0, -w2, w1, w2, 0.0, -w0, -w1, w0, 0.0};
        double W2[9];
#pragma unroll
        for (int i = 0; i < 3; i++)
#pragma unroll
            for (int j = 0; j < 3; j++) {
                double s2 = 0.0;
#pragma unroll
                for (int k = 0; k < 3; k++) s2 += Wm[i * 3 + k] * Wm[k * 3 + j];
                W2[i * 3 + j] = s2;
            }
        double dr[9];
#pragma unroll
        for (int i = 0; i < 9; i++)
            dr[i] = ((i % 4) == 0 ? 1.0 : 0.0) + Ac * Wm[i] + Bc * W2[i];
        double Rl[9], Tl[3];
#pragma unroll
        for (int i = 0; i < 9; i++) Rl[i] = g_R[i];
#pragma unroll
        for (int i = 0; i < 3; i++) Tl[i] = g_t[i];
#pragma unroll
        for (int i = 0; i < 3; i++) {
#pragma unroll
            for (int j = 0; j < 3; j++) {
                double s2 = 0.0;
#pragma unroll
                for (int k = 0; k < 3; k++) s2 += dr[i * 3 + k] * Rl[k * 3 + j];
                g_Rn[i * 3 + j] = s2;
            }
            g_tn[i] = dr[i * 3] * Tl[0] + dr[i * 3 + 1] * Tl[1] + dr[i * 3 + 2] * Tl[2] + sdelta[i];
        }
    }
    __syncwarp();
    if (lane < 29) g_acc[lane] = 0.0;
    if (lane < 2)  g_tacc[lane] = 0.0;
}

// ---------------- trial cost for candidate pose ----------------
__global__ void __launch_bounds__(128) k_trial(const float* __restrict__ p3D,
                                               const float* __restrict__ fref,
                                               const float* __restrict__ Km, int N) {
    int tid = threadIdx.x, lane = tid & 31, warp = tid >> 5;
    float R[9], T[3];
#pragma unroll
    for (int i = 0; i < 9; i++) R[i] = (float)g_Rn[i];
#pragma unroll
    for (int i = 0; i < 3; i++) T[i] = (float)g_tn[i];
    float fx = Km[0], fy = Km[4], cx = Km[2], cy = Km[5];

    double cD = 0.0, cC = 0.0;
    int wg = blockIdx.x * 4 + warp, nw = gridDim.x * 4;
    const float4* __restrict__ B4 = (const float4*)g_fqT;
    const float4* __restrict__ F4 = (const float4*)fref;

    for (int pt = wg; pt < N; pt += nw) {
        float Px = p3D[3 * pt], Py = p3D[3 * pt + 1], Pz = p3D[3 * pt + 2];
        float x_ = R[0] * Px + R[1] * Py + R[2] * Pz + T[0];
        float y_ = R[3] * Px + R[4] * Py + R[5] * Pz + T[1];
        float d  = R[6] * Px + R[7] * Py + R[8] * Pz + T[2];
        float izd = 1.0f / d;
        float px = x_ * izd * fx + cx;
        float py = y_ * izd * fy + cy;
        if (!inImage(px, py)) continue;

        int o[4]; float w[4];
        bilin4(px, py, o, w);
        float4 f4 = make_float4(0, 0, 0, 0);
#pragma unroll
        for (int k = 0; k < 4; k++) {
            float4 p = __ldg(&B4[o[k] + lane]);
            f4.x += w[k] * p.x; f4.y += w[k] * p.y; f4.z += w[k] * p.z; f4.w += w[k] * p.w;
        }
        float4 r4 = __ldg(&F4[pt * 32 + lane]);
        float s[3];
        s[0] = dot4(f4, f4);
        s[1] = dot4(f4, r4);
        s[2] = dot4(r4, r4);
        warpAllReduce<3>(s);
        if (lane == 0) {
            float inorm = 1.0f / fmaxf(sqrtf(s[0]), 1e-12f);
            float irn   = 1.0f / fmaxf(sqrtf(s[2]), 1e-12f);
            float errsq = s[0] * inorm * inorm - 2.0f * s[1] * inorm * irn + s[2] * irn * irn;
            cD += (double)errsq;
            cC += 1.0;
        }
    }
    __shared__ double sD[4], sC[4];
    if (lane == 0) { sD[warp] = cD; sC[warp] = cC; }
    __syncthreads();
    if (tid == 0) {
        atomicAdd(&g_tacc[0], sD[0] + sD[1] + sD[2] + sD[3]);
        atomicAdd(&g_tacc[1], sC[0] + sC[1] + sC[2] + sC[3]);
    }
}

// ---------------- final costs + output ----------------
__global__ void __launch_bounds__(128) k_final(const float* __restrict__ p3D,
                                               const float* __restrict__ fref,
                                               const float* __restrict__ Km,
                                               int N, float* __restrict__ out) {
    int tid = threadIdx.x, lane = tid & 31, warp = tid >> 5;
    double cn = g_tacc[0] / g_tacc[1];
    bool accPrev = (cn <= g_costbest);
    float R[9], T[3];
#pragma unroll
    for (int i = 0; i < 9; i++) R[i] = (float)(accPrev ? g_Rn[i] : g_R[i]);
#pragma unroll
    for (int i = 0; i < 3; i++) T[i] = (float)(accPrev ? g_tn[i] : g_t[i]);
    float fx = Km[0], fy = Km[4], cx = Km[2], cy = Km[5];

    if (blockIdx.x == 0 && tid == 0) {
#pragma unroll
        for (int i = 0; i < 9; i++) out[i] = (float)(accPrev ? g_Rn[i] : g_R[i]);
#pragma unroll
        for (int i = 0; i < 3; i++) out[9 + i] = (float)(accPrev ? g_tn[i] : g_t[i]);
    }
    const float NANF = __int_as_float(0x7fc00000);

    int wg = blockIdx.x * 4 + warp, nw = gridDim.x * 4;
    const float4* __restrict__ B4 = (const float4*)g_fqT;
    const float4* __restrict__ F4 = (const float4*)fref;

    for (int pt = wg; pt < N; pt += nw) {
        float pix = g_p2init[2 * pt], piy = g_p2init[2 * pt + 1];
        float Px = p3D[3 * pt], Py = p3D[3 * pt + 1], Pz = p3D[3 * pt + 2];
        float x_ = R[0] * Px + R[1] * Py + R[2] * Pz + T[0];
        float y_ = R[3] * Px + R[4] * Py + R[5] * Pz + T[1];
        float d  = R[6] * Px + R[7] * Py + R[8] * Pz + T[2];
        float izd = 1.0f / d;
        float pfx = x_ * izd * fx + cx;
        float pfy = y_ * izd * fy + cy;

        int oi[4], of_[4];
        float wi[4], wf[4];
        bilin4(pix, piy, oi, wi);
        bilin4(pfx, pfy, of_, wf);

        float4 fi4 = make_float4(0, 0, 0, 0);
        float4 ff4 = make_float4(0, 0, 0, 0);
#pragma unroll
        for (int k = 0; k < 4; k++) {
            float4 pi = __ldg(&B4[oi[k] + lane]);
            float4 pf = __ldg(&B4[of_[k] + lane]);
            fi4.x += wi[k] * pi.x; fi4.y += wi[k] * pi.y; fi4.z += wi[k] * pi.z; fi4.w += wi[k] * pi.w;
            ff4.x += wf[k] * pf.x; ff4.y += wf[k] * pf.y; ff4.z += wf[k] * pf.z; ff4.w += wf[k] * pf.w;
        }
        float4 r4 = __ldg(&F4[pt * 32 + lane]);
        float s[5];
        s[0] = dot4(fi4, fi4);
        s[1] = dot4(fi4, r4);
        s[2] = dot4(ff4, ff4);
        s[3] = dot4(ff4, r4);
        s[4] = dot4(r4, r4);
        warpAllReduce<5>(s);
        if (lane == 0) {
            float irn = 1.0f / fmaxf(sqrtf(s[4]), 1e-12f);
            float ini = 1.0f / fmaxf(sqrtf(s[0]), 1e-12f);
            float inf_ = 1.0f / fmaxf(sqrtf(s[2]), 1e-12f);
            float rr = s[4] * irn * irn;
            float ci = rr - 2.0f * s[1] * ini * irn + s[0] * ini * ini;
            float cf = rr - 2.0f * s[3] * inf_ * irn + s[2] * inf_ * inf_;
            out[12 + pt]     = inImage(pix, piy) ? ci : NANF;
            out[12 + N + pt] = inImage(pfx, pfy) ? cf : NANF;
        }
    }
}

// ---------------- launch ----------------
extern "C" void kernel_launch(void* const* d_in, const int* in_sizes, int n_in,
                              void* d_out, int out_size) {
    const float* p3D  = (const float*)d_in[0];
    const float* fref = (const float*)d_in[1];
    const float* fq   = (const float*)d_in[2];
    const float* Km   = (const float*)d_in[3];
    const float* R0   = (const float*)d_in[4];
    const float* t0   = (const float*)d_in[5];
    float* out = (float*)d_out;
    int N = in_sizes[0] / 3;
    if (N > MAXN) N = MAXN;

    k_init<<<1, 32>>>(R0, t0);
    k_transpose<<<NHW / 64, 256>>>(fq);
    for (int i = 0; i < 8; i++) {
        k_main<<<500, 128>>>(p3D, fref, Km, N, (i == 0) ? 1 : 0);
        k_solve<<<1, 32>>>(i);
        k_trial<<<500, 128>>>(p3D, fref, Km, N);
    }
    k_final<<<500, 128>>>(p3D, fref, Km, N, out);
}

// round 4
// speedup vs baseline: 6.1433x; 1.2797x over previous
#include <cuda_runtime.h>
#include <math.h>

#define NC   128
#define WW   512
#define HH   512
#define NHW  (HH*WW)
#define MAXN 10000

// ---------------- persistent device state ----------------
__device__ __align__(256) float g_fqT[NC * NHW];  // (pixel, channel) layout
__device__ float  g_p2init[2 * MAXN];
__device__ double g_acc[29];    // [0..20] Hess uptri, [21..26] Grad, [27] cost, [28] count
__device__ double g_tacc[2];    // trial cost sum, count
__device__ double g_costbest;
__device__ float  g_R[9], g_t[3], g_Rn[9], g_tn[3];
__device__ float  g_lam, g_jac[6];
__device__ unsigned int g_count;

__constant__ int c_hi[21] = {0,0,0,0,0,0, 1,1,1,1,1, 2,2,2,2, 3,3,3, 4,4, 5};
__constant__ int c_hj[21] = {0,1,2,3,4,5, 1,2,3,4,5, 2,3,4,5, 3,4,5, 4,5, 5};

// ---------------- helpers ----------------
__device__ __forceinline__ float dot4(float4 a, float4 b) {
    return a.x * b.x + a.y * b.y + a.z * b.z + a.w * b.w;
}

template <int NV>
__device__ __forceinline__ void warpAllReduce(float* v) {
#pragma unroll
    for (int off = 16; off > 0; off >>= 1)
#pragma unroll
        for (int i = 0; i < NV; i++) v[i] += __shfl_xor_sync(0xffffffffu, v[i], off);
}

__device__ __forceinline__ float selJ0(int k, float fxz, float fxz2, float x, float y, float z) {
    switch (k) {
        case 0: return fxz;
        case 1: return 0.0f;
        case 2: return fxz2;
        case 3: return fxz2 * y;
        case 4: return fxz * z - fxz2 * x;
        default: return -fxz * y;
    }
}
__device__ __forceinline__ float selJ1(int k, float fyz, float fyz2, float x, float y, float z) {
    switch (k) {
        case 0: return 0.0f;
        case 1: return fyz;
        case 2: return fyz2;
        case 3: return -fyz * z + fyz2 * y;
        case 4: return -fyz2 * x;
        default: return fyz * x;
    }
}

__device__ __forceinline__ bool inImage(float px, float py) {
    return (px >= 1.0f) && (px < 511.0f) && (py >= 1.0f) && (py < 511.0f);
}

__device__ __forceinline__ void bilin4(float px, float py, int* o, float* w) {
    float x0f = fminf(fmaxf(floorf(px), 0.0f), 511.0f);
    float y0f = fminf(fmaxf(floorf(py), 0.0f), 511.0f);
    float x1f = fminf(x0f + 1.0f, 511.0f);
    float y1f = fminf(y0f + 1.0f, 511.0f);
    float wx = px - x0f, wy = py - y0f;
    int x0 = (int)x0f, x1 = (int)x1f, y0 = (int)y0f, y1 = (int)y1f;
    o[0] = (y0 * WW + x0) * 32;
    o[1] = (y0 * WW + x1) * 32;
    o[2] = (y1 * WW + x0) * 32;
    o[3] = (y1 * WW + x1) * 32;
    w[0] = (1.0f - wx) * (1.0f - wy);
    w[1] = wx * (1.0f - wy);
    w[2] = (1.0f - wx) * wy;
    w[3] = wx * wy;
}

// ---------------- init ----------------
__global__ void k_init(const float* __restrict__ R0, const float* __restrict__ t0) {
    int i = threadIdx.x;
    if (i < 9) { g_R[i] = R0[i]; g_Rn[i] = R0[i]; }
    if (i < 3) { g_t[i] = t0[i]; g_tn[i] = t0[i]; }
    if (i == 0) {
        g_lam = 0.01f; g_costbest = -1e300;
        g_tacc[0] = 0.0; g_tacc[1] = 1.0;
        g_count = 0u;
    }
    if (i < 29) g_acc[i] = 0.0;
}

// ---------------- transpose (C,H,W) -> (H*W, C) ----------------
__global__ void __launch_bounds__(256) k_transpose(const float* __restrict__ fq) {
    __shared__ float sh[64][NC + 1];
    int pix0 = blockIdx.x * 64;
    int tid = threadIdx.x;
    int px = tid & 63;
    int crow = tid >> 6;
#pragma unroll
    for (int cb = 0; cb < NC; cb += 4) {
        int c = cb + crow;
        sh[px][c] = fq[c * NHW + pix0 + px];
    }
    __syncthreads();
    int c2 = tid & 127;
    int prow = tid >> 7;
#pragma unroll
    for (int pb = 0; pb < 64; pb += 2) {
        int p = pb + prow;
        g_fqT[(pix0 + p) * NC + c2] = sh[p][c2];
    }
}

// ---------------- fused fp32 solve (runs on one thread of the last block) ----------------
__device__ void do_solve(int iter) {
    volatile double* acc = g_acc;
    // commit / reject previous candidate
    if (iter > 0) {
        double cn = g_tacc[0] / g_tacc[1];
        bool a = (cn <= g_costbest);
        float l = g_lam * (a ? 0.1f : 10.0f);
        g_lam = fminf(fmaxf(l, 1e-8f), 1e4f);
        if (a) {
#pragma unroll
            for (int i = 0; i < 9; i++) g_R[i] = g_Rn[i];
#pragma unroll
            for (int i = 0; i < 3; i++) g_t[i] = g_tn[i];
            g_costbest = cn;
        }
    } else {
        g_costbest = acc[27] / acc[28];
    }

    float jac[6];
    if (iter == 0) {
        const int dix[6] = {0, 6, 11, 15, 18, 20};
#pragma unroll
        for (int i = 0; i < 6; i++) {
            jac[i] = 1.0f / (1.0f + sqrtf((float)acc[dix[i]]));
            g_jac[i] = jac[i];
        }
    } else {
#pragma unroll
        for (int i = 0; i < 6; i++) jac[i] = g_jac[i];
    }

    float A[6][7];
    {
        int idx = 0;
#pragma unroll
        for (int i = 0; i < 6; i++)
#pragma unroll
            for (int j = i; j < 6; j++) {
                float v = (float)acc[idx++] * jac[i] * jac[j];
                A[i][j] = v;
                A[j][i] = v;
            }
    }
    float lam = g_lam;
#pragma unroll
    for (int i = 0; i < 6; i++) {
        float d = A[i][i];
        A[i][i] = d + (d + 1e-9f) * lam;
        A[i][6] = -(float)acc[21 + i] * jac[i];
    }
    // GE with partial pivoting (fp32)
    for (int col = 0; col < 6; col++) {
        int piv = col;
        float best = fabsf(A[col][col]);
        for (int r = col + 1; r < 6; r++) {
            float v = fabsf(A[r][col]);
            if (v > best) { best = v; piv = r; }
        }
        if (piv != col)
            for (int j = 0; j < 7; j++) { float t = A[col][j]; A[col][j] = A[piv][j]; A[piv][j] = t; }
        float ip = 1.0f / A[col][col];
        for (int r = col + 1; r < 6; r++) {
            float f = A[r][col] * ip;
            for (int j = col; j < 7; j++) A[r][j] -= f * A[col][j];
        }
    }
    float x[6];
#pragma unroll
    for (int i = 5; i >= 0; i--) {
        float v = A[i][6];
#pragma unroll
        for (int j = 0; j < 6; j++)
            if (j > i) v -= A[i][j] * x[j];
        x[i] = v / A[i][i];
    }
    float delta[6];
#pragma unroll
    for (int i = 0; i < 6; i++) delta[i] = x[i] * jac[i];

    // SO(3) exp (fp32)
    float w0 = delta[3], w1 = delta[4], w2 = delta[5];
    float th2 = w0 * w0 + w1 * w1 + w2 * w2;
    float th = sqrtf(th2);
    float Ac, Bc;
    if (th < 1e-7f) { Ac = 1.0f; Bc = 0.5f; }
    else            { Ac = sinf(th) / th; Bc = (1.0f - cosf(th)) / th2; }
    float Wm[9] = {0.0f, -w2, w1, w2, 0.0f, -w0, -w1, w0, 0.0f};
    float W2[9];
#pragma unroll
    for (int i = 0; i < 3; i++)
#pragma unroll
        for (int j = 0; j < 3; j++) {
            float s2 = 0.0f;
#pragma unroll
            for (int k = 0; k < 3; k++) s2 += Wm[i * 3 + k] * Wm[k * 3 + j];
            W2[i * 3 + j] = s2;
        }
    float dr[9];
#pragma unroll
    for (int i = 0; i < 9; i++)
        dr[i] = ((i % 4) == 0 ? 1.0f : 0.0f) + Ac * Wm[i] + Bc * W2[i];

    float Rl[9], Tl[3];
#pragma unroll
    for (int i = 0; i < 9; i++) Rl[i] = g_R[i];
#pragma unroll
    for (int i = 0; i < 3; i++) Tl[i] = g_t[i];
#pragma unroll
    for (int i = 0; i < 3; i++) {
#pragma unroll
        for (int j = 0; j < 3; j++) {
            float s2 = 0.0f;
#pragma unroll
            for (int k = 0; k < 3; k++) s2 += dr[i * 3 + k] * Rl[k * 3 + j];
            g_Rn[i * 3 + j] = s2;
        }
        g_tn[i] = dr[i * 3] * Tl[0] + dr[i * 3 + 1] * Tl[1] + dr[i * 3 + 2] * Tl[2] + delta[i];
    }
    // reset accumulators for next iteration
#pragma unroll
    for (int i = 0; i < 29; i++) g_acc[i] = 0.0;
    g_tacc[0] = 0.0;
    g_tacc[1] = 0.0;
    g_count = 0u;
}

// ---------------- main LM accumulation (+ fused solve in last block) ----------------
__global__ void __launch_bounds__(128) k_main(const float* __restrict__ p3D,
                                              const float* __restrict__ fref,
                                              const float* __restrict__ Km,
                                              int N, int iter) {
    int tid = threadIdx.x, lane = tid & 31, warp = tid >> 5;
    // local accept decision for previous trial (same data the fused solve will use)
    double cn = g_tacc[0] / g_tacc[1];
    bool accPrev = (cn <= g_costbest);
    float R[9], T[3];
#pragma unroll
    for (int i = 0; i < 9; i++) R[i] = accPrev ? g_Rn[i] : g_R[i];
#pragma unroll
    for (int i = 0; i < 3; i++) T[i] = accPrev ? g_tn[i] : g_t[i];
    float fx = Km[0], fy = Km[4], cx = Km[2], cy = Km[5];

    int hi = 0, hj = 0;
    if (lane < 21) { hi = c_hi[lane]; hj = c_hj[lane]; }
    else if (lane < 27) { hj = lane - 21; }

    double accD = 0.0;
    int wg = blockIdx.x * 4 + warp, nw = gridDim.x * 4;
    const float4* __restrict__ B4 = (const float4*)g_fqT;
    const float4* __restrict__ F4 = (const float4*)fref;
    int isIter0 = (iter == 0);

    for (int pt = wg; pt < N; pt += nw) {
        float Px = p3D[3 * pt], Py = p3D[3 * pt + 1], Pz = p3D[3 * pt + 2];
        float x_ = R[0] * Px + R[1] * Py + R[2] * Pz + T[0];
        float y_ = R[3] * Px + R[4] * Py + R[5] * Pz + T[1];
        float d  = R[6] * Px + R[7] * Py + R[8] * Pz + T[2];
        float izd = 1.0f / d;
        float px = x_ * izd * fx + cx;
        float py = y_ * izd * fy + cy;
        if (isIter0 && lane == 0) { g_p2init[2 * pt] = px; g_p2init[2 * pt + 1] = py; }
        if (!inImage(px, py)) continue;

        float x0f = fminf(fmaxf(floorf(px), 0.0f), 511.0f);
        float y0f = fminf(fmaxf(floorf(py), 0.0f), 511.0f);
        float x1f = fminf(x0f + 1.0f, 511.0f);
        float y1f = fminf(y0f + 1.0f, 511.0f);
        float wx = px - x0f, wy = py - y0f;
        int x0 = (int)x0f, x1 = (int)x1f, y0 = (int)y0f, y1 = (int)y1f;
        int colo[4] = {(x0 > 0 ? x0 - 1 : 0) * 32, x0 * 32, x1 * 32,
                       (x1 < 511 ? x1 + 1 : 511) * 32};
        int rowo[4] = {(y0 > 0 ? y0 - 1 : 0) * (WW * 32), y0 * (WW * 32), y1 * (WW * 32),
                       (y1 < 511 ? y1 + 1 : 511) * (WW * 32)};
        float w00 = (1.0f - wx) * (1.0f - wy), w01 = wx * (1.0f - wy);
        float w10 = (1.0f - wx) * wy,          w11 = wx * wy;

        // combined (bilinear x sobel) weights over the 4x4 patch
        float wgx[16], wgy[16];
#pragma unroll
        for (int k = 0; k < 16; k++) { wgx[k] = 0.0f; wgy[k] = 0.0f; }
        const float KX[3][3] = {{-0.125f, 0.0f, 0.125f}, {-0.25f, 0.0f, 0.25f}, {-0.125f, 0.0f, 0.125f}};
        const float KY[3][3] = {{-0.125f, -0.25f, -0.125f}, {0.0f, 0.0f, 0.0f}, {0.125f, 0.25f, 0.125f}};
        float wb[2][2] = {{w00, w01}, {w10, w11}};
#pragma unroll
        for (int a = 0; a < 2; a++)
#pragma unroll
            for (int b = 0; b < 2; b++) {
                float wc = wb[a][b];
#pragma unroll
                for (int u = 0; u < 3; u++)
#pragma unroll
                    for (int v = 0; v < 3; v++) {
                        wgx[(a + u) * 4 + (b + v)] += wc * KX[u][v];
                        wgy[(a + u) * 4 + (b + v)] += wc * KY[u][v];
                    }
            }

        float4 f4  = make_float4(0, 0, 0, 0);
        float4 gx4 = make_float4(0, 0, 0, 0);
        float4 gy4 = make_float4(0, 0, 0, 0);
#pragma unroll
        for (int k = 0; k < 16; k++) {
            float4 p = __ldg(&B4[rowo[k >> 2] + colo[k & 3] + lane]);
            gx4.x += wgx[k] * p.x; gx4.y += wgx[k] * p.y; gx4.z += wgx[k] * p.z; gx4.w += wgx[k] * p.w;
            gy4.x += wgy[k] * p.x; gy4.y += wgy[k] * p.y; gy4.z += wgy[k] * p.z; gy4.w += wgy[k] * p.w;
            if (k == 5 || k == 6 || k == 9 || k == 10) {
                float wf = (k == 5) ? w00 : (k == 6) ? w01 : (k == 9) ? w10 : w11;
                f4.x += wf * p.x; f4.y += wf * p.y; f4.z += wf * p.z; f4.w += wf * p.w;
            }
        }
        float4 r4 = __ldg(&F4[pt * 32 + lane]);

        float s[10];
        s[0] = dot4(f4, f4);   s[1] = dot4(f4, gx4);  s[2] = dot4(f4, gy4);
        s[3] = dot4(gx4, gx4); s[4] = dot4(gx4, gy4); s[5] = dot4(gy4, gy4);
        s[6] = dot4(gx4, r4);  s[7] = dot4(gy4, r4);  s[8] = dot4(f4, r4);
        s[9] = dot4(r4, r4);
        warpAllReduce<10>(s);

        float norm  = fmaxf(sqrtf(s[0]), 1e-12f);
        float rnorm = fmaxf(sqrtf(s[9]), 1e-12f);
        float inorm = 1.0f / norm, irn = 1.0f / rnorm;
        float projx = s[1] * inorm, projy = s[2] * inorm;
        float nf2 = s[0] * inorm * inorm;
        float sc  = s[8] * inorm * irn;
        float in2 = inorm * inorm;
        float fac = 2.0f - nf2;
        float Mxx = (s[3] - projx * projx * fac) * in2;
        float Mxy = (s[4] - projx * projy * fac) * in2;
        float Myy = (s[5] - projy * projy * fac) * in2;
        float coef = 1.0f - nf2 + sc;
        float g2x = (projx * coef - s[6] * irn) * inorm;
        float g2y = (projy * coef - s[7] * irn) * inorm;

        float fxz = fx * izd, fxz2 = -fx * x_ * izd * izd;
        float fyz = fy * izd, fyz2 = -fy * y_ * izd * izd;

        float val;
        if (lane < 21) {
            float a0 = selJ0(hi, fxz, fxz2, x_, y_, d);
            float a1 = selJ1(hi, fyz, fyz2, x_, y_, d);
            float b0 = selJ0(hj, fxz, fxz2, x_, y_, d);
            float b1 = selJ1(hj, fyz, fyz2, x_, y_, d);
            float u  = Mxx * a0 + Mxy * a1;
            float vv = Mxy * a0 + Myy * a1;
            val = u * b0 + vv * b1;
        } else if (lane < 27) {
            float b0 = selJ0(hj, fxz, fxz2, x_, y_, d);
            float b1 = selJ1(hj, fyz, fyz2, x_, y_, d);
            val = g2x * b0 + g2y * b1;
        } else if (lane == 27) {
            val = nf2 - 2.0f * sc + s[9] * irn * irn;
        } else if (lane == 28) {
            val = 1.0f;
        } else {
            val = 0.0f;
        }
        accD += (double)val;
    }

    __shared__ double sred[4][29];
    __shared__ bool s_last;
    if (lane < 29) sred[warp][lane] = accD;
    __syncthreads();
    if (warp == 0 && lane < 29) {
        double t2 = sred[0][lane] + sred[1][lane] + sred[2][lane] + sred[3][lane];
        atomicAdd(&g_acc[lane], t2);
    }
    __syncthreads();
    if (tid == 0) {
        __threadfence();
        unsigned int t = atomicAdd(&g_count, 1u);
        s_last = (t == gridDim.x - 1);
    }
    __syncthreads();
    if (s_last && tid == 0) {
        __threadfence();
        do_solve(iter);
    }
}

// ---------------- trial cost for candidate pose ----------------
__global__ void __launch_bounds__(128) k_trial(const float* __restrict__ p3D,
                                               const float* __restrict__ fref,
                                               const float* __restrict__ Km, int N) {
    int tid = threadIdx.x, lane = tid & 31, warp = tid >> 5;
    float R[9], T[3];
#pragma unroll
    for (int i = 0; i < 9; i++) R[i] = g_Rn[i];
#pragma unroll
    for (int i = 0; i < 3; i++) T[i] = g_tn[i];
    float fx = Km[0], fy = Km[4], cx = Km[2], cy = Km[5];

    double cD = 0.0, cC = 0.0;
    int wg = blockIdx.x * 4 + warp, nw = gridDim.x * 4;
    const float4* __restrict__ B4 = (const float4*)g_fqT;
    const float4* __restrict__ F4 = (const float4*)fref;

    for (int pt = wg; pt < N; pt += nw) {
        float Px = p3D[3 * pt], Py = p3D[3 * pt + 1], Pz = p3D[3 * pt + 2];
        float x_ = R[0] * Px + R[1] * Py + R[2] * Pz + T[0];
        float y_ = R[3] * Px + R[4] * Py + R[5] * Pz + T[1];
        float d  = R[6] * Px + R[7] * Py + R[8] * Pz + T[2];
        float izd = 1.0f / d;
        float px = x_ * izd * fx + cx;
        float py = y_ * izd * fy + cy;
        if (!inImage(px, py)) continue;

        int o[4]; float w[4];
        bilin4(px, py, o, w);
        float4 f4 = make_float4(0, 0, 0, 0);
#pragma unroll
        for (int k = 0; k < 4; k++) {
            float4 p = __ldg(&B4[o[k] + lane]);
            f4.x += w[k] * p.x; f4.y += w[k] * p.y; f4.z += w[k] * p.z; f4.w += w[k] * p.w;
        }
        float4 r4 = __ldg(&F4[pt * 32 + lane]);
        float s[3];
        s[0] = dot4(f4, f4);
        s[1] = dot4(f4, r4);
        s[2] = dot4(r4, r4);
        warpAllReduce<3>(s);
        if (lane == 0) {
            float inorm = 1.0f / fmaxf(sqrtf(s[0]), 1e-12f);
            float irn   = 1.0f / fmaxf(sqrtf(s[2]), 1e-12f);
            float errsq = s[0] * inorm * inorm - 2.0f * s[1] * inorm * irn + s[2] * irn * irn;
            cD += (double)errsq;
            cC += 1.0;
        }
    }
    __shared__ double sD[4], sC[4];
    if (lane == 0) { sD[warp] = cD; sC[warp] = cC; }
    __syncthreads();
    if (tid == 0) {
        atomicAdd(&g_tacc[0], sD[0] + sD[1] + sD[2] + sD[3]);
        atomicAdd(&g_tacc[1], sC[0] + sC[1] + sC[2] + sC[3]);
    }
}

// ---------------- final costs + output ----------------
__global__ void __launch_bounds__(128) k_final(const float* __restrict__ p3D,
                                               const float* __restrict__ fref,
                                               const float* __restrict__ Km,
                                               int N, float* __restrict__ out) {
    int tid = threadIdx.x, lane = tid & 31, warp = tid >> 5;
    double cn = g_tacc[0] / g_tacc[1];
    bool accPrev = (cn <= g_costbest);
    float R[9], T[3];
#pragma unroll
    for (int i = 0; i < 9; i++) R[i] = accPrev ? g_Rn[i] : g_R[i];
#pragma unroll
    for (int i = 0; i < 3; i++) T[i] = accPrev ? g_tn[i] : g_t[i];
    float fx = Km[0], fy = Km[4], cx = Km[2], cy = Km[5];

    if (blockIdx.x == 0 && tid == 0) {
#pragma unroll
        for (int i = 0; i < 9; i++) out[i] = R[i];
#pragma unroll
        for (int i = 0; i < 3; i++) out[9 + i] = T[i];
    }
    const float NANF = __int_as_float(0x7fc00000);

    int wg = blockIdx.x * 4 + warp, nw = gridDim.x * 4;
    const float4* __restrict__ B4 = (const float4*)g_fqT;
    const float4* __restrict__ F4 = (const float4*)fref;

    for (int pt = wg; pt < N; pt += nw) {
        float pix = g_p2init[2 * pt], piy = g_p2init[2 * pt + 1];
        float Px = p3D[3 * pt], Py = p3D[3 * pt + 1], Pz = p3D[3 * pt + 2];
        float x_ = R[0] * Px + R[1] * Py + R[2] * Pz + T[0];
        float y_ = R[3] * Px + R[4] * Py + R[5] * Pz + T[1];
        float d  = R[6] * Px + R[7] * Py + R[8] * Pz + T[2];
        float izd = 1.0f / d;
        float pfx = x_ * izd * fx + cx;
        float pfy = y_ * izd * fy + cy;

        int oi[4], of_[4];
        float wi[4], wf[4];
        bilin4(pix, piy, oi, wi);
        bilin4(pfx, pfy, of_, wf);

        float4 fi4 = make_float4(0, 0, 0, 0);
        float4 ff4 = make_float4(0, 0, 0, 0);
#pragma unroll
        for (int k = 0; k < 4; k++) {
            float4 pi = __ldg(&B4[oi[k] + lane]);
            float4 pf = __ldg(&B4[of_[k] + lane]);
            fi4.x += wi[k] * pi.x; fi4.y += wi[k] * pi.y; fi4.z += wi[k] * pi.z; fi4.w += wi[k] * pi.w;
            ff4.x += wf[k] * pf.x; ff4.y += wf[k] * pf.y; ff4.z += wf[k] * pf.z; ff4.w += wf[k] * pf.w;
        }
        float4 r4 = __ldg(&F4[pt * 32 + lane]);
        float s[5];
        s[0] = dot4(fi4, fi4);
        s[1] = dot4(fi4, r4);
        s[2] = dot4(ff4, ff4);
        s[3] = dot4(ff4, r4);
        s[4] = dot4(r4, r4);
        warpAllReduce<5>(s);
        if (lane == 0) {
            float irn = 1.0f / fmaxf(sqrtf(s[4]), 1e-12f);
            float ini = 1.0f / fmaxf(sqrtf(s[0]), 1e-12f);
            float inf_ = 1.0f / fmaxf(sqrtf(s[2]), 1e-12f);
            float rr = s[4] * irn * irn;
            float ci = rr - 2.0f * s[1] * ini * irn + s[0] * ini * ini;
            float cf = rr - 2.0f * s[3] * inf_ * irn + s[2] * inf_ * inf_;
            out[12 + pt]     = inImage(pix, piy) ? ci : NANF;
            out[12 + N + pt] = inImage(pfx, pfy) ? cf : NANF;
        }
    }
}

// ---------------- launch ----------------
extern "C" void kernel_launch(void* const* d_in, const int* in_sizes, int n_in,
                              void* d_out, int out_size) {
    const float* p3D  = (const float*)d_in[0];
    const float* fref = (const float*)d_in[1];
    const float* fq   = (const float*)d_in[2];
    const float* Km   = (const float*)d_in[3];
    const float* R0   = (const float*)d_in[4];
    const float* t0   = (const float*)d_in[5];
    float* out = (float*)d_out;
    int N = in_sizes[0] / 3;
    if (N > MAXN) N = MAXN;

    k_init<<<1, 32>>>(R0, t0);
    k_transpose<<<NHW / 64, 256>>>(fq);
    for (int i = 0; i < 8; i++) {
        k_main<<<500, 128>>>(p3D, fref, Km, N, i);
        k_trial<<<500, 128>>>(p3D, fref, Km, N);
    }
    k_final<<<500, 128>>>(p3D, fref, Km, N, out);
}

// round 5
// speedup vs baseline: 6.3323x; 1.0308x over previous
#include <cuda_runtime.h>
#include <cuda_fp16.h>
#include <math.h>

#define NC   128
#define WW   512
#define HH   512
#define NHW  (HH*WW)
#define MAXN 10000

// ---------------- persistent device state ----------------
__device__ __align__(16) __half g_fqH[NC * NHW];  // (pixel, channel) layout, fp16
__device__ float  g_p2init[2 * MAXN];
__device__ double g_acc[29];    // [0..20] Hess uptri, [21..26] Grad, [27] cost, [28] count
__device__ double g_tacc[2];    // trial cost sum, count
__device__ double g_costbest;
__device__ float  g_R[9], g_t[3], g_Rn[9], g_tn[3];
__device__ float  g_lam, g_jac[6];
__device__ unsigned int g_count;

__constant__ int c_hi[21] = {0,0,0,0,0,0, 1,1,1,1,1, 2,2,2,2, 3,3,3, 4,4, 5};
__constant__ int c_hj[21] = {0,1,2,3,4,5, 1,2,3,4,5, 2,3,4,5, 3,4,5, 4,5, 5};

// ---------------- helpers ----------------
struct F4 { float a, b, c, d; };

__device__ __forceinline__ F4 loadPix(const uint2* __restrict__ B, int off, int lane) {
    uint2 raw = __ldg(B + off + lane);
    __half2 h0 = *(__half2*)&raw.x;
    __half2 h1 = *(__half2*)&raw.y;
    float2 f0 = __half22float2(h0);
    float2 f1 = __half22float2(h1);
    F4 r; r.a = f0.x; r.b = f0.y; r.c = f1.x; r.d = f1.y;
    return r;
}

__device__ __forceinline__ float dot4f(F4 x, F4 y) {
    return x.a * y.a + x.b * y.b + x.c * y.c + x.d * y.d;
}

template <int NV>
__device__ __forceinline__ void warpAllReduce(float* v) {
#pragma unroll
    for (int off = 16; off > 0; off >>= 1)
#pragma unroll
        for (int i = 0; i < NV; i++) v[i] += __shfl_xor_sync(0xffffffffu, v[i], off);
}

__device__ __forceinline__ float selJ0(int k, float fxz, float fxz2, float x, float y, float z) {
    switch (k) {
        case 0: return fxz;
        case 1: return 0.0f;
        case 2: return fxz2;
        case 3: return fxz2 * y;
        case 4: return fxz * z - fxz2 * x;
        default: return -fxz * y;
    }
}
__device__ __forceinline__ float selJ1(int k, float fyz, float fyz2, float x, float y, float z) {
    switch (k) {
        case 0: return 0.0f;
        case 1: return fyz;
        case 2: return fyz2;
        case 3: return -fyz * z + fyz2 * y;
        case 4: return -fyz2 * x;
        default: return fyz * x;
    }
}

__device__ __forceinline__ bool inImage(float px, float py) {
    return (px >= 1.0f) && (px < 511.0f) && (py >= 1.0f) && (py < 511.0f);
}

// bilinear footprint in 8-byte (uint2 = 4 half-channels) units: 32 per pixel
__device__ __forceinline__ void bilin4(float px, float py, int* o, float* w) {
    float x0f = fminf(fmaxf(floorf(px), 0.0f), 511.0f);
    float y0f = fminf(fmaxf(floorf(py), 0.0f), 511.0f);
    float x1f = fminf(x0f + 1.0f, 511.0f);
    float y1f = fminf(y0f + 1.0f, 511.0f);
    float wx = px - x0f, wy = py - y0f;
    int x0 = (int)x0f, x1 = (int)x1f, y0 = (int)y0f, y1 = (int)y1f;
    o[0] = (y0 * WW + x0) * 32;
    o[1] = (y0 * WW + x1) * 32;
    o[2] = (y1 * WW + x0) * 32;
    o[3] = (y1 * WW + x1) * 32;
    w[0] = (1.0f - wx) * (1.0f - wy);
    w[1] = wx * (1.0f - wy);
    w[2] = (1.0f - wx) * wy;
    w[3] = wx * wy;
}

// ---------------- init ----------------
__global__ void k_init(const float* __restrict__ R0, const float* __restrict__ t0) {
    int i = threadIdx.x;
    if (i < 9) { g_R[i] = R0[i]; g_Rn[i] = R0[i]; }
    if (i < 3) { g_t[i] = t0[i]; g_tn[i] = t0[i]; }
    if (i == 0) {
        g_lam = 0.01f; g_costbest = -1e300;
        g_tacc[0] = 0.0; g_tacc[1] = 1.0;
        g_count = 0u;
    }
    if (i < 29) g_acc[i] = 0.0;
}

// ---------------- transpose (C,H,W) f32 -> (H*W, C) f16 ----------------
__global__ void __launch_bounds__(256) k_transpose(const float* __restrict__ fq) {
    __shared__ float sh[64][NC + 1];
    int pix0 = blockIdx.x * 64;
    int tid = threadIdx.x;
    int px = tid & 63;
    int crow = tid >> 6;
#pragma unroll
    for (int cb = 0; cb < NC; cb += 4) {
        int c = cb + crow;
        sh[px][c] = fq[c * NHW + pix0 + px];
    }
    __syncthreads();
    int cpair = tid & 63;      // 64 half2 per pixel
    int prow = tid >> 6;       // 0..3
    __half2* out2 = (__half2*)g_fqH;
#pragma unroll
    for (int pb = 0; pb < 64; pb += 4) {
        int p = pb + prow;
        __half2 h = __floats2half2_rn(sh[p][2 * cpair], sh[p][2 * cpair + 1]);
        out2[(size_t)(pix0 + p) * 64 + cpair] = h;
    }
}

// ---------------- fused fp32 solve (one thread of last-arriving block) ----------------
__device__ void do_solve(int iter) {
    volatile double* acc = g_acc;
    if (iter > 0) {
        double cn = g_tacc[0] / g_tacc[1];
        bool a = (cn <= g_costbest);
        float l = g_lam * (a ? 0.1f : 10.0f);
        g_lam = fminf(fmaxf(l, 1e-8f), 1e4f);
        if (a) {
#pragma unroll
            for (int i = 0; i < 9; i++) g_R[i] = g_Rn[i];
#pragma unroll
            for (int i = 0; i < 3; i++) g_t[i] = g_tn[i];
            g_costbest = cn;
        }
    } else {
        g_costbest = acc[27] / acc[28];
    }

    float jac[6];
    if (iter == 0) {
        const int dix[6] = {0, 6, 11, 15, 18, 20};
#pragma unroll
        for (int i = 0; i < 6; i++) {
            jac[i] = 1.0f / (1.0f + sqrtf((float)acc[dix[i]]));
            g_jac[i] = jac[i];
        }
    } else {
#pragma unroll
        for (int i = 0; i < 6; i++) jac[i] = g_jac[i];
    }

    float A[6][7];
    {
        int idx = 0;
#pragma unroll
        for (int i = 0; i < 6; i++)
#pragma unroll
            for (int j = i; j < 6; j++) {
                float v = (float)acc[idx++] * jac[i] * jac[j];
                A[i][j] = v;
                A[j][i] = v;
            }
    }
    float lam = g_lam;
#pragma unroll
    for (int i = 0; i < 6; i++) {
        float d = A[i][i];
        A[i][i] = d + (d + 1e-9f) * lam;
        A[i][6] = -(float)acc[21 + i] * jac[i];
    }
    for (int col = 0; col < 6; col++) {
        int piv = col;
        float best = fabsf(A[col][col]);
        for (int r = col + 1; r < 6; r++) {
            float v = fabsf(A[r][col]);
            if (v > best) { best = v; piv = r; }
        }
        if (piv != col)
            for (int j = 0; j < 7; j++) { float t = A[col][j]; A[col][j] = A[piv][j]; A[piv][j] = t; }
        float ip = 1.0f / A[col][col];
        for (int r = col + 1; r < 6; r++) {
            float f = A[r][col] * ip;
            for (int j = col; j < 7; j++) A[r][j] -= f * A[col][j];
        }
    }
    float x[6];
#pragma unroll
    for (int i = 5; i >= 0; i--) {
        float v = A[i][6];
#pragma unroll
        for (int j = 0; j < 6; j++)
            if (j > i) v -= A[i][j] * x[j];
        x[i] = v / A[i][i];
    }
    float delta[6];
#pragma unroll
    for (int i = 0; i < 6; i++) delta[i] = x[i] * jac[i];

    float w0 = delta[3], w1 = delta[4], w2 = delta[5];
    float th2 = w0 * w0 + w1 * w1 + w2 * w2;
    float th = sqrtf(th2);
    float Ac, Bc;
    if (th < 1e-7f) { Ac = 1.0f; Bc = 0.5f; }
    else            { Ac = sinf(th) / th; Bc = (1.0f - cosf(th)) / th2; }
    float Wm[9] = {0.0f, -w2, w1, w2, 0.0f, -w0, -w1, w0, 0.0f};
    float W2[9];
#pragma unroll
    for (int i = 0; i < 3; i++)
#pragma unroll
        for (int j = 0; j < 3; j++) {
            float s2 = 0.0f;
#pragma unroll
            for (int k = 0; k < 3; k++) s2 += Wm[i * 3 + k] * Wm[k * 3 + j];
            W2[i * 3 + j] = s2;
        }
    float dr[9];
#pragma unroll
    for (int i = 0; i < 9; i++)
        dr[i] = ((i % 4) == 0 ? 1.0f : 0.0f) + Ac * Wm[i] + Bc * W2[i];

    float Rl[9], Tl[3];
#pragma unroll
    for (int i = 0; i < 9; i++) Rl[i] = g_R[i];
#pragma unroll
    for (int i = 0; i < 3; i++) Tl[i] = g_t[i];
#pragma unroll
    for (int i = 0; i < 3; i++) {
#pragma unroll
        for (int j = 0; j < 3; j++) {
            float s2 = 0.0f;
#pragma unroll
            for (int k = 0; k < 3; k++) s2 += dr[i * 3 + k] * Rl[k * 3 + j];
            g_Rn[i * 3 + j] = s2;
        }
        g_tn[i] = dr[i * 3] * Tl[0] + dr[i * 3 + 1] * Tl[1] + dr[i * 3 + 2] * Tl[2] + delta[i];
    }
#pragma unroll
    for (int i = 0; i < 29; i++) g_acc[i] = 0.0;
    g_tacc[0] = 0.0;
    g_tacc[1] = 0.0;
    g_count = 0u;
}

// ---------------- main LM accumulation (+ fused solve) ----------------
__global__ void __launch_bounds__(256) k_main(const float* __restrict__ p3D,
                                              const float* __restrict__ fref,
                                              const float* __restrict__ Km,
                                              int N, int iter) {
    int tid = threadIdx.x, lane = tid & 31, warp = tid >> 5;
    double cn = g_tacc[0] / g_tacc[1];
    bool accPrev = (cn <= g_costbest);
    float R[9], T[3];
#pragma unroll
    for (int i = 0; i < 9; i++) R[i] = accPrev ? g_Rn[i] : g_R[i];
#pragma unroll
    for (int i = 0; i < 3; i++) T[i] = accPrev ? g_tn[i] : g_t[i];
    float fx = Km[0], fy = Km[4], cx = Km[2], cy = Km[5];

    int hi = 0, hj = 0;
    if (lane < 21) { hi = c_hi[lane]; hj = c_hj[lane]; }
    else if (lane < 27) { hj = lane - 21; }

    double accD = 0.0;
    int wg = blockIdx.x * 8 + warp, nw = gridDim.x * 8;
    const uint2* __restrict__ B = (const uint2*)g_fqH;
    const float4* __restrict__ F4p = (const float4*)fref;
    int isIter0 = (iter == 0);

    for (int pt = wg; pt < N; pt += nw) {
        float Px = p3D[3 * pt], Py = p3D[3 * pt + 1], Pz = p3D[3 * pt + 2];
        float x_ = R[0] * Px + R[1] * Py + R[2] * Pz + T[0];
        float y_ = R[3] * Px + R[4] * Py + R[5] * Pz + T[1];
        float d  = R[6] * Px + R[7] * Py + R[8] * Pz + T[2];
        float izd = 1.0f / d;
        float px = x_ * izd * fx + cx;
        float py = y_ * izd * fy + cy;
        if (isIter0 && lane == 0) { g_p2init[2 * pt] = px; g_p2init[2 * pt + 1] = py; }
        if (!inImage(px, py)) continue;

        float x0f = fminf(fmaxf(floorf(px), 0.0f), 511.0f);
        float y0f = fminf(fmaxf(floorf(py), 0.0f), 511.0f);
        float x1f = fminf(x0f + 1.0f, 511.0f);
        float y1f = fminf(y0f + 1.0f, 511.0f);
        float wx = px - x0f, wy = py - y0f;
        int x0 = (int)x0f, x1 = (int)x1f, y0 = (int)y0f, y1 = (int)y1f;
        int colo[4] = {(x0 > 0 ? x0 - 1 : 0) * 32, x0 * 32, x1 * 32,
                       (x1 < 511 ? x1 + 1 : 511) * 32};
        int rowo[4] = {(y0 > 0 ? y0 - 1 : 0) * (WW * 32), y0 * (WW * 32), y1 * (WW * 32),
                       (y1 < 511 ? y1 + 1 : 511) * (WW * 32)};
        float w00 = (1.0f - wx) * (1.0f - wy), w01 = wx * (1.0f - wy);
        float w10 = (1.0f - wx) * wy,          w11 = wx * wy;

        float wgx[16], wgy[16];
#pragma unroll
        for (int k = 0; k < 16; k++) { wgx[k] = 0.0f; wgy[k] = 0.0f; }
        const float KX[3][3] = {{-0.125f, 0.0f, 0.125f}, {-0.25f, 0.0f, 0.25f}, {-0.125f, 0.0f, 0.125f}};
        const float KY[3][3] = {{-0.125f, -0.25f, -0.125f}, {0.0f, 0.0f, 0.0f}, {0.125f, 0.25f, 0.125f}};
        float wb[2][2] = {{w00, w01}, {w10, w11}};
#pragma unroll
        for (int a = 0; a < 2; a++)
#pragma unroll
            for (int b = 0; b < 2; b++) {
                float wc = wb[a][b];
#pragma unroll
                for (int u = 0; u < 3; u++)
#pragma unroll
                    for (int v = 0; v < 3; v++) {
                        wgx[(a + u) * 4 + (b + v)] += wc * KX[u][v];
                        wgy[(a + u) * 4 + (b + v)] += wc * KY[u][v];
                    }
            }

        F4 f4  = {0, 0, 0, 0};
        F4 gx4 = {0, 0, 0, 0};
        F4 gy4 = {0, 0, 0, 0};
#pragma unroll
        for (int k = 0; k < 16; k++) {
            F4 p = loadPix(B, rowo[k >> 2] + colo[k & 3], lane);
            gx4.a += wgx[k] * p.a; gx4.b += wgx[k] * p.b; gx4.c += wgx[k] * p.c; gx4.d += wgx[k] * p.d;
            gy4.a += wgy[k] * p.a; gy4.b += wgy[k] * p.b; gy4.c += wgy[k] * p.c; gy4.d += wgy[k] * p.d;
            if (k == 5 || k == 6 || k == 9 || k == 10) {
                float wf = (k == 5) ? w00 : (k == 6) ? w01 : (k == 9) ? w10 : w11;
                f4.a += wf * p.a; f4.b += wf * p.b; f4.c += wf * p.c; f4.d += wf * p.d;
            }
        }
        float4 rr4 = __ldg(&F4p[pt * 32 + lane]);
        F4 r4 = {rr4.x, rr4.y, rr4.z, rr4.w};

        float s[10];
        s[0] = dot4f(f4, f4);   s[1] = dot4f(f4, gx4);  s[2] = dot4f(f4, gy4);
        s[3] = dot4f(gx4, gx4); s[4] = dot4f(gx4, gy4); s[5] = dot4f(gy4, gy4);
        s[6] = dot4f(gx4, r4);  s[7] = dot4f(gy4, r4);  s[8] = dot4f(f4, r4);
        s[9] = dot4f(r4, r4);
        warpAllReduce<10>(s);

        float norm  = fmaxf(sqrtf(s[0]), 1e-12f);
        float rnorm = fmaxf(sqrtf(s[9]), 1e-12f);
        float inorm = 1.0f / norm, irn = 1.0f / rnorm;
        float projx = s[1] * inorm, projy = s[2] * inorm;
        float nf2 = s[0] * inorm * inorm;
        float sc  = s[8] * inorm * irn;
        float in2 = inorm * inorm;
        float fac = 2.0f - nf2;
        float Mxx = (s[3] - projx * projx * fac) * in2;
        float Mxy = (s[4] - projx * projy * fac) * in2;
        float Myy = (s[5] - projy * projy * fac) * in2;
        float coef = 1.0f - nf2 + sc;
        float g2x = (projx * coef - s[6] * irn) * inorm;
        float g2y = (projy * coef - s[7] * irn) * inorm;

        float fxz = fx * izd, fxz2 = -fx * x_ * izd * izd;
        float fyz = fy * izd, fyz2 = -fy * y_ * izd * izd;

        float val;
        if (lane < 21) {
            float a0 = selJ0(hi, fxz, fxz2, x_, y_, d);
            float a1 = selJ1(hi, fyz, fyz2, x_, y_, d);
            float b0 = selJ0(hj, fxz, fxz2, x_, y_, d);
            float b1 = selJ1(hj, fyz, fyz2, x_, y_, d);
            float u  = Mxx * a0 + Mxy * a1;
            float vv = Mxy * a0 + Myy * a1;
            val = u * b0 + vv * b1;
        } else if (lane < 27) {
            float b0 = selJ0(hj, fxz, fxz2, x_, y_, d);
            float b1 = selJ1(hj, fyz, fyz2, x_, y_, d);
            val = g2x * b0 + g2y * b1;
        } else if (lane == 27) {
            val = nf2 - 2.0f * sc + s[9] * irn * irn;
        } else if (lane == 28) {
            val = 1.0f;
        } else {
            val = 0.0f;
        }
        accD += (double)val;
    }

    __shared__ double sred[8][29];
    __shared__ bool s_last;
    if (lane < 29) sred[warp][lane] = accD;
    __syncthreads();
    if (warp == 0 && lane < 29) {
        double t2 = 0.0;
#pragma unroll
        for (int w2i = 0; w2i < 8; w2i++) t2 += sred[w2i][lane];
        atomicAdd(&g_acc[lane], t2);
    }
    __syncthreads();
    if (tid == 0) {
        __threadfence();
        unsigned int t = atomicAdd(&g_count, 1u);
        s_last = (t == gridDim.x - 1);
    }
    __syncthreads();
    if (s_last && tid == 0) {
        __threadfence();
        do_solve(iter);
    }
}

// ---------------- trial cost for candidate pose ----------------
__global__ void __launch_bounds__(256) k_trial(const float* __restrict__ p3D,
                                               const float* __restrict__ fref,
                                               const float* __restrict__ Km, int N) {
    int tid = threadIdx.x, lane = tid & 31, warp = tid >> 5;
    float R[9], T[3];
#pragma unroll
    for (int i = 0; i < 9; i++) R[i] = g_Rn[i];
#pragma unroll
    for (int i = 0; i < 3; i++) T[i] = g_tn[i];
    float fx = Km[0], fy = Km[4], cx = Km[2], cy = Km[5];

    double cD = 0.0, cC = 0.0;
    int wg = blockIdx.x * 8 + warp, nw = gridDim.x * 8;
    const uint2* __restrict__ B = (const uint2*)g_fqH;
    const float4* __restrict__ F4p = (const float4*)fref;

    for (int pt = wg; pt < N; pt += nw) {
        float Px = p3D[3 * pt], Py = p3D[3 * pt + 1], Pz = p3D[3 * pt + 2];
        float x_ = R[0] * Px + R[1] * Py + R[2] * Pz + T[0];
        float y_ = R[3] * Px + R[4] * Py + R[5] * Pz + T[1];
        float d  = R[6] * Px + R[7] * Py + R[8] * Pz + T[2];
        float izd = 1.0f / d;
        float px = x_ * izd * fx + cx;
        float py = y_ * izd * fy + cy;
        if (!inImage(px, py)) continue;

        int o[4]; float w[4];
        bilin4(px, py, o, w);
        F4 f4 = {0, 0, 0, 0};
#pragma unroll
        for (int k = 0; k < 4; k++) {
            F4 p = loadPix(B, o[k], lane);
            f4.a += w[k] * p.a; f4.b += w[k] * p.b; f4.c += w[k] * p.c; f4.d += w[k] * p.d;
        }
        float4 rr4 = __ldg(&F4p[pt * 32 + lane]);
        F4 r4 = {rr4.x, rr4.y, rr4.z, rr4.w};
        float s[3];
        s[0] = dot4f(f4, f4);
        s[1] = dot4f(f4, r4);
        s[2] = dot4f(r4, r4);
        warpAllReduce<3>(s);
        if (lane == 0) {
            float inorm = 1.0f / fmaxf(sqrtf(s[0]), 1e-12f);
            float irn   = 1.0f / fmaxf(sqrtf(s[2]), 1e-12f);
            float errsq = s[0] * inorm * inorm - 2.0f * s[1] * inorm * irn + s[2] * irn * irn;
            cD += (double)errsq;
            cC += 1.0;
        }
    }
    __shared__ double sD[8], sC[8];
    if (lane == 0) { sD[warp] = cD; sC[warp] = cC; }
    __syncthreads();
    if (tid == 0) {
        double a = 0.0, b = 0.0;
#pragma unroll
        for (int i = 0; i < 8; i++) { a += sD[i]; b += sC[i]; }
        atomicAdd(&g_tacc[0], a);
        atomicAdd(&g_tacc[1], b);
    }
}

// ---------------- final costs + output ----------------
__global__ void __launch_bounds__(256) k_final(const float* __restrict__ p3D,
                                               const float* __restrict__ fref,
                                               const float* __restrict__ Km,
                                               int N, float* __restrict__ out) {
    int tid = threadIdx.x, lane = tid & 31, warp = tid >> 5;
    double cn = g_tacc[0] / g_tacc[1];
    bool accPrev = (cn <= g_costbest);
    float R[9], T[3];
#pragma unroll
    for (int i = 0; i < 9; i++) R[i] = accPrev ? g_Rn[i] : g_R[i];
#pragma unroll
    for (int i = 0; i < 3; i++) T[i] = accPrev ? g_tn[i] : g_t[i];
    float fx = Km[0], fy = Km[4], cx = Km[2], cy = Km[5];

    if (blockIdx.x == 0 && tid == 0) {
#pragma unroll
        for (int i = 0; i < 9; i++) out[i] = R[i];
#pragma unroll
        for (int i = 0; i < 3; i++) out[9 + i] = T[i];
    }
    const float NANF = __int_as_float(0x7fc00000);

    int wg = blockIdx.x * 8 + warp, nw = gridDim.x * 8;
    const uint2* __restrict__ B = (const uint2*)g_fqH;
    const float4* __restrict__ F4p = (const float4*)fref;

    for (int pt = wg; pt < N; pt += nw) {
        float pix = g_p2init[2 * pt], piy = g_p2init[2 * pt + 1];
        float Px = p3D[3 * pt], Py = p3D[3 * pt + 1], Pz = p3D[3 * pt + 2];
        float x_ = R[0] * Px + R[1] * Py + R[2] * Pz + T[0];
        float y_ = R[3] * Px + R[4] * Py + R[5] * Pz + T[1];
        float d  = R[6] * Px + R[7] * Py + R[8] * Pz + T[2];
        float izd = 1.0f / d;
        float pfx = x_ * izd * fx + cx;
        float pfy = y_ * izd * fy + cy;

        int oi[4], of_[4];
        float wi[4], wf[4];
        bilin4(pix, piy, oi, wi);
        bilin4(pfx, pfy, of_, wf);

        F4 fi4 = {0, 0, 0, 0};
        F4 ff4 = {0, 0, 0, 0};
#pragma unroll
        for (int k = 0; k < 4; k++) {
            F4 pi = loadPix(B, oi[k], lane);
            F4 pf = loadPix(B, of_[k], lane);
            fi4.a += wi[k] * pi.a; fi4.b += wi[k] * pi.b; fi4.c += wi[k] * pi.c; fi4.d += wi[k] * pi.d;
            ff4.a += wf[k] * pf.a; ff4.b += wf[k] * pf.b; ff4.c += wf[k] * pf.c; ff4.d += wf[k] * pf.d;
        }
        float4 rr4 = __ldg(&F4p[pt * 32 + lane]);
        F4 r4 = {rr4.x, rr4.y, rr4.z, rr4.w};
        float s[5];
        s[0] = dot4f(fi4, fi4);
        s[1] = dot4f(fi4, r4);
        s[2] = dot4f(ff4, ff4);
        s[3] = dot4f(ff4, r4);
        s[4] = dot4f(r4, r4);
        warpAllReduce<5>(s);
        if (lane == 0) {
            float irn = 1.0f / fmaxf(sqrtf(s[4]), 1e-12f);
            float ini = 1.0f / fmaxf(sqrtf(s[0]), 1e-12f);
            float inf_ = 1.0f / fmaxf(sqrtf(s[2]), 1e-12f);
            float rr = s[4] * irn * irn;
            float ci = rr - 2.0f * s[1] * ini * irn + s[0] * ini * ini;
            float cf = rr - 2.0f * s[3] * inf_ * irn + s[2] * inf_ * inf_;
            out[12 + pt]     = inImage(pix, piy) ? ci : NANF;
            out[12 + N + pt] = inImage(pfx, pfy) ? cf : NANF;
        }
    }
}

// ---------------- launch ----------------
extern "C" void kernel_launch(void* const* d_in, const int* in_sizes, int n_in,
                              void* d_out, int out_size) {
    const float* p3D  = (const float*)d_in[0];
    const float* fref = (const float*)d_in[1];
    const float* fq   = (const float*)d_in[2];
    const float* Km   = (const float*)d_in[3];
    const float* R0   = (const float*)d_in[4];
    const float* t0   = (const float*)d_in[5];
    float* out = (float*)d_out;
    int N = in_sizes[0] / 3;
    if (N > MAXN) N = MAXN;

    k_init<<<1, 32>>>(R0, t0);
    k_transpose<<<NHW / 64, 256>>>(fq);
    for (int i = 0; i < 8; i++) {
        k_main<<<625, 256>>>(p3D, fref, Km, N, i);
        k_trial<<<625, 256>>>(p3D, fref, Km, N);
    }
    k_final<<<625, 256>>>(p3D, fref, Km, N, out);
}

// round 6
// speedup vs baseline: 6.9217x; 1.0931x over previous
#include <cuda_runtime.h>
#include <cuda_fp16.h>
#include <math.h>

#define NC   128
#define WW   512
#define HH   512
#define NHW  (HH*WW)
#define MAXN 10000

// ---------------- persistent device state ----------------
__device__ __align__(16) __half g_fqH[NC * NHW];  // (pixel, channel) layout, fp16
__device__ float  g_p2init[2 * MAXN];
__device__ double g_acc[29];    // [0..20] Hess uptri, [21..26] Grad, [27] cost, [28] count
__device__ double g_tacc[2];    // trial cost sum, count
__device__ double g_costbest;
__device__ float  g_R[9], g_t[3], g_Rn[9], g_tn[3];
__device__ float  g_lam, g_jac[6];
__device__ unsigned int g_count;

__constant__ int c_hi[21] = {0,0,0,0,0,0, 1,1,1,1,1, 2,2,2,2, 3,3,3, 4,4, 5};
__constant__ int c_hj[21] = {0,1,2,3,4,5, 1,2,3,4,5, 2,3,4,5, 3,4,5, 4,5, 5};

// ---------------- helpers ----------------
__device__ __forceinline__ void unpack8(uint4 raw, float* p) {
    const __half2* h = (const __half2*)&raw;
#pragma unroll
    for (int j = 0; j < 4; j++) {
        float2 f = __half22float2(h[j]);
        p[2 * j]     = f.x;
        p[2 * j + 1] = f.y;
    }
}

// butterfly reduce over a 16-lane half-warp; result in all 16 lanes
template <int NV>
__device__ __forceinline__ void halfReduce(float* v) {
#pragma unroll
    for (int off = 8; off > 0; off >>= 1)
#pragma unroll
        for (int i = 0; i < NV; i++) v[i] += __shfl_xor_sync(0xffffffffu, v[i], off);
}

__device__ __forceinline__ float selJ0(int k, float fxz, float fxz2, float x, float y, float z) {
    switch (k) {
        case 0: return fxz;
        case 1: return 0.0f;
        case 2: return fxz2;
        case 3: return fxz2 * y;
        case 4: return fxz * z - fxz2 * x;
        default: return -fxz * y;
    }
}
__device__ __forceinline__ float selJ1(int k, float fyz, float fyz2, float x, float y, float z) {
    switch (k) {
        case 0: return 0.0f;
        case 1: return fyz;
        case 2: return fyz2;
        case 3: return -fyz * z + fyz2 * y;
        case 4: return -fyz2 * x;
        default: return fyz * x;
    }
}

__device__ __forceinline__ bool inImage(float px, float py) {
    return (px >= 1.0f) && (px < 511.0f) && (py >= 1.0f) && (py < 511.0f);
}

// bilinear footprint in uint4 (=8 half-channels) units: 16 per pixel
__device__ __forceinline__ void bilin4(float px, float py, int* o, float* w) {
    float x0f = fminf(fmaxf(floorf(px), 0.0f), 511.0f);
    float y0f = fminf(fmaxf(floorf(py), 0.0f), 511.0f);
    float x1f = fminf(x0f + 1.0f, 511.0f);
    float y1f = fminf(y0f + 1.0f, 511.0f);
    float wx = px - x0f, wy = py - y0f;
    int x0 = (int)x0f, x1 = (int)x1f, y0 = (int)y0f, y1 = (int)y1f;
    o[0] = (y0 * WW + x0) * 16;
    o[1] = (y0 * WW + x1) * 16;
    o[2] = (y1 * WW + x0) * 16;
    o[3] = (y1 * WW + x1) * 16;
    w[0] = (1.0f - wx) * (1.0f - wy);
    w[1] = wx * (1.0f - wy);
    w[2] = (1.0f - wx) * wy;
    w[3] = wx * wy;
}

// ---------------- init ----------------
__global__ void k_init(const float* __restrict__ R0, const float* __restrict__ t0) {
    int i = threadIdx.x;
    if (i < 9) { g_R[i] = R0[i]; g_Rn[i] = R0[i]; }
    if (i < 3) { g_t[i] = t0[i]; g_tn[i] = t0[i]; }
    if (i == 0) {
        g_lam = 0.01f; g_costbest = -1e300;
        g_tacc[0] = 0.0; g_tacc[1] = 1.0;
        g_count = 0u;
    }
    if (i < 29) g_acc[i] = 0.0;
}

// ---------------- transpose (C,H,W) f32 -> (H*W, C) f16 ----------------
__global__ void __launch_bounds__(256) k_transpose(const float* __restrict__ fq) {
    __shared__ float sh[64][NC + 1];
    int pix0 = blockIdx.x * 64;
    int tid = threadIdx.x;
    int px = tid & 63;
    int crow = tid >> 6;
#pragma unroll
    for (int cb = 0; cb < NC; cb += 4) {
        int c = cb + crow;
        sh[px][c] = fq[c * NHW + pix0 + px];
    }
    __syncthreads();
    int cpair = tid & 63;      // 64 half2 per pixel
    int prow = tid >> 6;       // 0..3
    __half2* out2 = (__half2*)g_fqH;
#pragma unroll
    for (int pb = 0; pb < 64; pb += 4) {
        int p = pb + prow;
        __half2 h = __floats2half2_rn(sh[p][2 * cpair], sh[p][2 * cpair + 1]);
        out2[(size_t)(pix0 + p) * 64 + cpair] = h;
    }
}

// ---------------- fused fp32 solve (one thread of last-arriving block) ----------------
__device__ void do_solve(int iter) {
    volatile double* acc = g_acc;
    if (iter > 0) {
        double cn = g_tacc[0] / g_tacc[1];
        bool a = (cn <= g_costbest);
        float l = g_lam * (a ? 0.1f : 10.0f);
        g_lam = fminf(fmaxf(l, 1e-8f), 1e4f);
        if (a) {
#pragma unroll
            for (int i = 0; i < 9; i++) g_R[i] = g_Rn[i];
#pragma unroll
            for (int i = 0; i < 3; i++) g_t[i] = g_tn[i];
            g_costbest = cn;
        }
    } else {
        g_costbest = acc[27] / acc[28];
    }

    float jac[6];
    if (iter == 0) {
        const int dix[6] = {0, 6, 11, 15, 18, 20};
#pragma unroll
        for (int i = 0; i < 6; i++) {
            jac[i] = 1.0f / (1.0f + sqrtf((float)acc[dix[i]]));
            g_jac[i] = jac[i];
        }
    } else {
#pragma unroll
        for (int i = 0; i < 6; i++) jac[i] = g_jac[i];
    }

    float A[6][7];
    {
        int idx = 0;
#pragma unroll
        for (int i = 0; i < 6; i++)
#pragma unroll
            for (int j = i; j < 6; j++) {
                float v = (float)acc[idx++] * jac[i] * jac[j];
                A[i][j] = v;
                A[j][i] = v;
            }
    }
    float lam = g_lam;
#pragma unroll
    for (int i = 0; i < 6; i++) {
        float d = A[i][i];
        A[i][i] = d + (d + 1e-9f) * lam;
        A[i][6] = -(float)acc[21 + i] * jac[i];
    }
    for (int col = 0; col < 6; col++) {
        int piv = col;
        float best = fabsf(A[col][col]);
        for (int r = col + 1; r < 6; r++) {
            float v = fabsf(A[r][col]);
            if (v > best) { best = v; piv = r; }
        }
        if (piv != col)
            for (int j = 0; j < 7; j++) { float t = A[col][j]; A[col][j] = A[piv][j]; A[piv][j] = t; }
        float ip = 1.0f / A[col][col];
        for (int r = col + 1; r < 6; r++) {
            float f = A[r][col] * ip;
            for (int j = col; j < 7; j++) A[r][j] -= f * A[col][j];
        }
    }
    float x[6];
#pragma unroll
    for (int i = 5; i >= 0; i--) {
        float v = A[i][6];
#pragma unroll
        for (int j = 0; j < 6; j++)
            if (j > i) v -= A[i][j] * x[j];
        x[i] = v / A[i][i];
    }
    float delta[6];
#pragma unroll
    for (int i = 0; i < 6; i++) delta[i] = x[i] * jac[i];

    float w0 = delta[3], w1 = delta[4], w2 = delta[5];
    float th2 = w0 * w0 + w1 * w1 + w2 * w2;
    float th = sqrtf(th2);
    float Ac, Bc;
    if (th < 1e-7f) { Ac = 1.0f; Bc = 0.5f; }
    else            { Ac = sinf(th) / th; Bc = (1.0f - cosf(th)) / th2; }
    float Wm[9] = {0.0f, -w2, w1, w2, 0.0f, -w0, -w1, w0, 0.0f};
    float W2[9];
#pragma unroll
    for (int i = 0; i < 3; i++)
#pragma unroll
        for (int j = 0; j < 3; j++) {
            float s2 = 0.0f;
#pragma unroll
            for (int k = 0; k < 3; k++) s2 += Wm[i * 3 + k] * Wm[k * 3 + j];
            W2[i * 3 + j] = s2;
        }
    float dr[9];
#pragma unroll
    for (int i = 0; i < 9; i++)
        dr[i] = ((i % 4) == 0 ? 1.0f : 0.0f) + Ac * Wm[i] + Bc * W2[i];

    float Rl[9], Tl[3];
#pragma unroll
    for (int i = 0; i < 9; i++) Rl[i] = g_R[i];
#pragma unroll
    for (int i = 0; i < 3; i++) Tl[i] = g_t[i];
#pragma unroll
    for (int i = 0; i < 3; i++) {
#pragma unroll
        for (int j = 0; j < 3; j++) {
            float s2 = 0.0f;
#pragma unroll
            for (int k = 0; k < 3; k++) s2 += dr[i * 3 + k] * Rl[k * 3 + j];
            g_Rn[i * 3 + j] = s2;
        }
        g_tn[i] = dr[i * 3] * Tl[0] + dr[i * 3 + 1] * Tl[1] + dr[i * 3 + 2] * Tl[2] + delta[i];
    }
#pragma unroll
    for (int i = 0; i < 29; i++) g_acc[i] = 0.0;
    g_tacc[0] = 0.0;
    g_tacc[1] = 0.0;
    g_count = 0u;
}

// value of accumulator slot idx (0..28) for one point
__device__ __forceinline__ float valForIdx(int idx, float Mxx, float Mxy, float Myy,
                                           float g2x, float g2y, float errsq,
                                           float fxz, float fxz2, float fyz, float fyz2,
                                           float x_, float y_, float d) {
    if (idx < 21) {
        int i = c_hi[idx], j = c_hj[idx];
        float a0 = selJ0(i, fxz, fxz2, x_, y_, d);
        float a1 = selJ1(i, fyz, fyz2, x_, y_, d);
        float b0 = selJ0(j, fxz, fxz2, x_, y_, d);
        float b1 = selJ1(j, fyz, fyz2, x_, y_, d);
        float u  = Mxx * a0 + Mxy * a1;
        float vv = Mxy * a0 + Myy * a1;
        return u * b0 + vv * b1;
    } else if (idx < 27) {
        int j = idx - 21;
        float b0 = selJ0(j, fxz, fxz2, x_, y_, d);
        float b1 = selJ1(j, fyz, fyz2, x_, y_, d);
        return g2x * b0 + g2y * b1;
    } else if (idx == 27) {
        return errsq;
    }
    return 1.0f;
}

// ---------------- main LM accumulation (+ fused solve), half-warp per point ----------------
__global__ void __launch_bounds__(256) k_main(const float* __restrict__ p3D,
                                              const float* __restrict__ fref,
                                              const float* __restrict__ Km,
                                              int N, int iter) {
    int tid = threadIdx.x, lane = tid & 31, warp = tid >> 5;
    int hl = lane & 15;
    int side = lane >> 4;
    int wid = blockIdx.x * 8 + warp;
    int pt = 2 * wid + side;
    bool vp = (pt < N);
    int ptc = vp ? pt : 0;

    double cn = g_tacc[0] / g_tacc[1];
    bool accPrev = (cn <= g_costbest);
    float R[9], T[3];
#pragma unroll
    for (int i = 0; i < 9; i++) R[i] = accPrev ? g_Rn[i] : g_R[i];
#pragma unroll
    for (int i = 0; i < 3; i++) T[i] = accPrev ? g_tn[i] : g_t[i];
    float fx = Km[0], fy = Km[4], cx = Km[2], cy = Km[5];

    float Px = p3D[3 * ptc], Py = p3D[3 * ptc + 1], Pz = p3D[3 * ptc + 2];
    float x_ = R[0] * Px + R[1] * Py + R[2] * Pz + T[0];
    float y_ = R[3] * Px + R[4] * Py + R[5] * Pz + T[1];
    float d  = R[6] * Px + R[7] * Py + R[8] * Pz + T[2];
    float izd0 = 1.0f / d;
    float px = x_ * izd0 * fx + cx;
    float py = y_ * izd0 * fy + cy;
    if (iter == 0 && hl == 0 && vp) { g_p2init[2 * pt] = px; g_p2init[2 * pt + 1] = py; }
    bool valid = vp && inImage(px, py);
    if (!valid) { px = 256.0f; py = 256.0f; d = 1.0f; }
    float izd = 1.0f / d;

    float x0f = floorf(px), y0f = floorf(py);
    float wx = px - x0f, wy = py - y0f;
    int x0 = (int)x0f, x1 = x0 + 1, y0 = (int)y0f, y1 = y0 + 1;
    int colo[4] = {(x0 - 1) * 16, x0 * 16, x1 * 16, (x1 < 511 ? x1 + 1 : 511) * 16};
    int rowo[4] = {(y0 - 1) * (WW * 16), y0 * (WW * 16), y1 * (WW * 16),
                   (y1 < 511 ? y1 + 1 : 511) * (WW * 16)};
    float w00 = (1.0f - wx) * (1.0f - wy), w01 = wx * (1.0f - wy);
    float w10 = (1.0f - wx) * wy,          w11 = wx * wy;

    float wgx[16], wgy[16];
#pragma unroll
    for (int k = 0; k < 16; k++) { wgx[k] = 0.0f; wgy[k] = 0.0f; }
    {
        const float KX[3][3] = {{-0.125f, 0.0f, 0.125f}, {-0.25f, 0.0f, 0.25f}, {-0.125f, 0.0f, 0.125f}};
        const float KY[3][3] = {{-0.125f, -0.25f, -0.125f}, {0.0f, 0.0f, 0.0f}, {0.125f, 0.25f, 0.125f}};
        float wb[2][2] = {{w00, w01}, {w10, w11}};
#pragma unroll
        for (int a = 0; a < 2; a++)
#pragma unroll
            for (int b = 0; b < 2; b++) {
                float wc = wb[a][b];
#pragma unroll
                for (int u = 0; u < 3; u++)
#pragma unroll
                    for (int v = 0; v < 3; v++) {
                        wgx[(a + u) * 4 + (b + v)] += wc * KX[u][v];
                        wgy[(a + u) * 4 + (b + v)] += wc * KY[u][v];
                    }
            }
    }

    const uint4* __restrict__ B = (const uint4*)g_fqH;
    float f8[8], gx8[8], gy8[8];
#pragma unroll
    for (int j = 0; j < 8; j++) { f8[j] = 0.0f; gx8[j] = 0.0f; gy8[j] = 0.0f; }
#pragma unroll
    for (int k = 0; k < 16; k++) {
        uint4 raw = __ldg(&B[rowo[k >> 2] + colo[k & 3] + hl]);
        float p[8];
        unpack8(raw, p);
        float ax = wgx[k], ay = wgy[k];
#pragma unroll
        for (int j = 0; j < 8; j++) { gx8[j] += ax * p[j]; gy8[j] += ay * p[j]; }
        if (k == 5 || k == 6 || k == 9 || k == 10) {
            float wf = (k == 5) ? w00 : (k == 6) ? w01 : (k == 9) ? w10 : w11;
#pragma unroll
            for (int j = 0; j < 8; j++) f8[j] += wf * p[j];
        }
    }
    float r8[8];
    {
        const float4* __restrict__ F4p = (const float4*)fref;
        float4 ra = __ldg(&F4p[ptc * 32 + 2 * hl]);
        float4 rb = __ldg(&F4p[ptc * 32 + 2 * hl + 1]);
        r8[0] = ra.x; r8[1] = ra.y; r8[2] = ra.z; r8[3] = ra.w;
        r8[4] = rb.x; r8[5] = rb.y; r8[6] = rb.z; r8[7] = rb.w;
    }

    float s[10];
#pragma unroll
    for (int i = 0; i < 10; i++) s[i] = 0.0f;
#pragma unroll
    for (int j = 0; j < 8; j++) {
        s[0] += f8[j] * f8[j];   s[1] += f8[j] * gx8[j];  s[2] += f8[j] * gy8[j];
        s[3] += gx8[j] * gx8[j]; s[4] += gx8[j] * gy8[j]; s[5] += gy8[j] * gy8[j];
        s[6] += gx8[j] * r8[j];  s[7] += gy8[j] * r8[j];  s[8] += f8[j] * r8[j];
        s[9] += r8[j] * r8[j];
    }
    halfReduce<10>(s);

    float norm  = fmaxf(sqrtf(s[0]), 1e-12f);
    float rnorm = fmaxf(sqrtf(s[9]), 1e-12f);
    float inorm = 1.0f / norm, irn = 1.0f / rnorm;
    float projx = s[1] * inorm, projy = s[2] * inorm;
    float nf2 = s[0] * inorm * inorm;
    float sc  = s[8] * inorm * irn;
    float in2 = inorm * inorm;
    float fac = 2.0f - nf2;
    float Mxx = (s[3] - projx * projx * fac) * in2;
    float Mxy = (s[4] - projx * projy * fac) * in2;
    float Myy = (s[5] - projy * projy * fac) * in2;
    float coef = 1.0f - nf2 + sc;
    float g2x = (projx * coef - s[6] * irn) * inorm;
    float g2y = (projy * coef - s[7] * irn) * inorm;
    float errsq = nf2 - 2.0f * sc + s[9] * irn * irn;

    float fxz = fx * izd, fxz2 = -fx * x_ * izd * izd;
    float fyz = fy * izd, fyz2 = -fy * y_ * izd * izd;
    float vf = valid ? 1.0f : 0.0f;

    double a0 = (double)(vf * valForIdx(hl, Mxx, Mxy, Myy, g2x, g2y, errsq,
                                        fxz, fxz2, fyz, fyz2, x_, y_, d));
    double a1 = 0.0;
    if (hl < 13)
        a1 = (double)(vf * valForIdx(hl + 16, Mxx, Mxy, Myy, g2x, g2y, errsq,
                                     fxz, fxz2, fyz, fyz2, x_, y_, d));
    // merge the two half-warps (two points)
    a0 += __shfl_down_sync(0xffffffffu, a0, 16);
    a1 += __shfl_down_sync(0xffffffffu, a1, 16);

    __shared__ double sred[8][29];
    __shared__ bool s_last;
    if (lane < 16) sred[warp][lane] = a0;
    if (lane < 13) sred[warp][16 + lane] = a1;
    __syncthreads();
    if (warp == 0 && lane < 29) {
        double t2 = 0.0;
#pragma unroll
        for (int w2i = 0; w2i < 8; w2i++) t2 += sred[w2i][lane];
        atomicAdd(&g_acc[lane], t2);
    }
    __syncthreads();
    if (tid == 0) {
        __threadfence();
        unsigned int t = atomicAdd(&g_count, 1u);
        s_last = (t == gridDim.x - 1);
    }
    __syncthreads();
    if (s_last && tid == 0) {
        __threadfence();
        do_solve(iter);
    }
}

// ---------------- trial cost for candidate pose, half-warp per point ----------------
__global__ void __launch_bounds__(256) k_trial(const float* __restrict__ p3D,
                                               const float* __restrict__ fref,
                                               const float* __restrict__ Km, int N) {
    int tid = threadIdx.x, lane = tid & 31, warp = tid >> 5;
    int hl = lane & 15, side = lane >> 4;
    int wid = blockIdx.x * 8 + warp;
    int pt = 2 * wid + side;
    bool vp = (pt < N);
    int ptc = vp ? pt : 0;

    float R[9], T[3];
#pragma unroll
    for (int i = 0; i < 9; i++) R[i] = g_Rn[i];
#pragma unroll
    for (int i = 0; i < 3; i++) T[i] = g_tn[i];
    float fx = Km[0], fy = Km[4], cx = Km[2], cy = Km[5];

    float Px = p3D[3 * ptc], Py = p3D[3 * ptc + 1], Pz = p3D[3 * ptc + 2];
    float x_ = R[0] * Px + R[1] * Py + R[2] * Pz + T[0];
    float y_ = R[3] * Px + R[4] * Py + R[5] * Pz + T[1];
    float d  = R[6] * Px + R[7] * Py + R[8] * Pz + T[2];
    float izd = 1.0f / d;
    float px = x_ * izd * fx + cx;
    float py = y_ * izd * fy + cy;
    bool valid = vp && inImage(px, py);
    if (!valid) { px = 256.0f; py = 256.0f; }

    int o[4]; float w[4];
    bilin4(px, py, o, w);
    const uint4* __restrict__ B = (const uint4*)g_fqH;
    float f8[8];
#pragma unroll
    for (int j = 0; j < 8; j++) f8[j] = 0.0f;
#pragma unroll
    for (int k = 0; k < 4; k++) {
        uint4 raw = __ldg(&B[o[k] + hl]);
        float p[8];
        unpack8(raw, p);
#pragma unroll
        for (int j = 0; j < 8; j++) f8[j] += w[k] * p[j];
    }
    float r8[8];
    {
        const float4* __restrict__ F4p = (const float4*)fref;
        float4 ra = __ldg(&F4p[ptc * 32 + 2 * hl]);
        float4 rb = __ldg(&F4p[ptc * 32 + 2 * hl + 1]);
        r8[0] = ra.x; r8[1] = ra.y; r8[2] = ra.z; r8[3] = ra.w;
        r8[4] = rb.x; r8[5] = rb.y; r8[6] = rb.z; r8[7] = rb.w;
    }
    float s[3] = {0.0f, 0.0f, 0.0f};
#pragma unroll
    for (int j = 0; j < 8; j++) {
        s[0] += f8[j] * f8[j];
        s[1] += f8[j] * r8[j];
        s[2] += r8[j] * r8[j];
    }
    halfReduce<3>(s);

    float inorm = 1.0f / fmaxf(sqrtf(s[0]), 1e-12f);
    float irn   = 1.0f / fmaxf(sqrtf(s[2]), 1e-12f);
    float errsq = s[0] * inorm * inorm - 2.0f * s[1] * inorm * irn + s[2] * irn * irn;
    float vf = valid ? 1.0f : 0.0f;

    double eD = (hl == 0) ? (double)(errsq * vf) : 0.0;
    double eC = (hl == 0) ? (double)vf : 0.0;
    eD += __shfl_down_sync(0xffffffffu, eD, 16);
    eC += __shfl_down_sync(0xffffffffu, eC, 16);

    __shared__ double sD[8], sC[8];
    if (lane == 0) { sD[warp] = eD; sC[warp] = eC; }
    __syncthreads();
    if (tid == 0) {
        double a = 0.0, b = 0.0;
#pragma unroll
        for (int i = 0; i < 8; i++) { a += sD[i]; b += sC[i]; }
        atomicAdd(&g_tacc[0], a);
        atomicAdd(&g_tacc[1], b);
    }
}

// ---------------- final costs + output, half-warp per point ----------------
__global__ void __launch_bounds__(256) k_final(const float* __restrict__ p3D,
                                               const float* __restrict__ fref,
                                               const float* __restrict__ Km,
                                               int N, float* __restrict__ out) {
    int tid = threadIdx.x, lane = tid & 31, warp = tid >> 5;
    int hl = lane & 15, side = lane >> 4;
    int wid = blockIdx.x * 8 + warp;
    int pt = 2 * wid + side;
    bool vp = (pt < N);
    int ptc = vp ? pt : 0;

    double cn = g_tacc[0] / g_tacc[1];
    bool accPrev = (cn <= g_costbest);
    float R[9], T[3];
#pragma unroll
    for (int i = 0; i < 9; i++) R[i] = accPrev ? g_Rn[i] : g_R[i];
#pragma unroll
    for (int i = 0; i < 3; i++) T[i] = accPrev ? g_tn[i] : g_t[i];
    float fx = Km[0], fy = Km[4], cx = Km[2], cy = Km[5];

    if (blockIdx.x == 0 && tid == 0) {
#pragma unroll
        for (int i = 0; i < 9; i++) out[i] = R[i];
#pragma unroll
        for (int i = 0; i < 3; i++) out[9 + i] = T[i];
    }
    const float NANF = __int_as_float(0x7fc00000);

    float pix = g_p2init[2 * ptc], piy = g_p2init[2 * ptc + 1];
    float Px = p3D[3 * ptc], Py = p3D[3 * ptc + 1], Pz = p3D[3 * ptc + 2];
    float x_ = R[0] * Px + R[1] * Py + R[2] * Pz + T[0];
    float y_ = R[3] * Px + R[4] * Py + R[5] * Pz + T[1];
    float d  = R[6] * Px + R[7] * Py + R[8] * Pz + T[2];
    float izd = 1.0f / d;
    float pfx = x_ * izd * fx + cx;
    float pfy = y_ * izd * fy + cy;

    bool vi = inImage(pix, piy);
    bool vfv = inImage(pfx, pfy);
    float pixc = vi ? pix : 256.0f, piyc = vi ? piy : 256.0f;
    float pfxc = vfv ? pfx : 256.0f, pfyc = vfv ? pfy : 256.0f;

    int oi[4], of_[4];
    float wi[4], wf[4];
    bilin4(pixc, piyc, oi, wi);
    bilin4(pfxc, pfyc, of_, wf);

    const uint4* __restrict__ B = (const uint4*)g_fqH;
    float fi8[8], ff8[8];
#pragma unroll
    for (int j = 0; j < 8; j++) { fi8[j] = 0.0f; ff8[j] = 0.0f; }
#pragma unroll
    for (int k = 0; k < 4; k++) {
        uint4 rawi = __ldg(&B[oi[k] + hl]);
        uint4 rawf = __ldg(&B[of_[k] + hl]);
        float pi[8], pf[8];
        unpack8(rawi, pi);
        unpack8(rawf, pf);
#pragma unroll
        for (int j = 0; j < 8; j++) {
            fi8[j] += wi[k] * pi[j];
            ff8[j] += wf[k] * pf[j];
        }
    }
    float r8[8];
    {
        const float4* __restrict__ F4p = (const float4*)fref;
        float4 ra = __ldg(&F4p[ptc * 32 + 2 * hl]);
        float4 rb = __ldg(&F4p[ptc * 32 + 2 * hl + 1]);
        r8[0] = ra.x; r8[1] = ra.y; r8[2] = ra.z; r8[3] = ra.w;
        r8[4] = rb.x; r8[5] = rb.y; r8[6] = rb.z; r8[7] = rb.w;
    }
    float s[5] = {0, 0, 0, 0, 0};
#pragma unroll
    for (int j = 0; j < 8; j++) {
        s[0] += fi8[j] * fi8[j];
        s[1] += fi8[j] * r8[j];
        s[2] += ff8[j] * ff8[j];
        s[3] += ff8[j] * r8[j];
        s[4] += r8[j] * r8[j];
    }
    halfReduce<5>(s);

    if (hl == 0 && vp) {
        float irn = 1.0f / fmaxf(sqrtf(s[4]), 1e-12f);
        float ini = 1.0f / fmaxf(sqrtf(s[0]), 1e-12f);
        float inf_ = 1.0f / fmaxf(sqrtf(s[2]), 1e-12f);
        float rr = s[4] * irn * irn;
        float ci = rr - 2.0f * s[1] * ini * irn + s[0] * ini * ini;
        float cf = rr - 2.0f * s[3] * inf_ * irn + s[2] * inf_ * inf_;
        out[12 + pt]     = vi  ? ci : NANF;
        out[12 + N + pt] = vfv ? cf : NANF;
    }
}

// ---------------- launch ----------------
extern "C" void kernel_launch(void* const* d_in, const int* in_sizes, int n_in,
                              void* d_out, int out_size) {
    const float* p3D  = (const float*)d_in[0];
    const float* fref = (const float*)d_in[1];
    const float* fq   = (const float*)d_in[2];
    const float* Km   = (const float*)d_in[3];
    const float* R0   = (const float*)d_in[4];
    const float* t0   = (const float*)d_in[5];
    float* out = (float*)d_out;
    int N = in_sizes[0] / 3;
    if (N > MAXN) N = MAXN;

    int grid = (N + 15) / 16;   // 8 warps/block * 2 pts/warp
    k_init<<<1, 32>>>(R0, t0);
    k_transpose<<<NHW / 64, 256>>>(fq);
    for (int i = 0; i < 8; i++) {
        k_main<<<grid, 256>>>(p3D, fref, Km, N, i);
        k_trial<<<grid, 256>>>(p3D, fref, Km, N);
    }
    k_final<<<grid, 256>>>(p3D, fref, Km, N, out);
}